// round 10
// baseline (speedup 1.0000x reference)
#include <cuda_runtime.h>
#include <cstdint>

#define B_TOT 2048
#define LN    128
#define CDIM  128
#define NH    4
#define HD    32
#define SCALEF 0.17677669529663687f   // 32^-0.5

typedef unsigned long long ull;

// ---------- f32x2 packed helpers ----------
__device__ __forceinline__ void fma2(ull& d, ull a, ull b) {
    asm("fma.rn.f32x2 %0, %1, %2, %0;" : "+l"(d) : "l"(a), "l"(b));
}
__device__ __forceinline__ ull pk2(float x, float y) {
    ull r; asm("mov.b64 %0, {%1, %2};" : "=l"(r) : "f"(x), "f"(y)); return r;
}
__device__ __forceinline__ float2 up2(ull u) {
    float2 f; asm("mov.b64 {%0, %1}, %2;" : "=f"(f.x), "=f"(f.y) : "l"(u)); return f;
}

// ---------- tf32 warp MMA ----------
__device__ __forceinline__ float tf32r(float f) {
    uint32_t u; asm("cvt.rna.tf32.f32 %0, %1;" : "=r"(u) : "f"(f));
    return __uint_as_float(u);
}
__device__ __forceinline__ void mma8(float* c, const float* a, float b0, float b1) {
    asm volatile(
        "mma.sync.aligned.m16n8k8.row.col.f32.tf32.tf32.f32 "
        "{%0,%1,%2,%3}, {%4,%5,%6,%7}, {%8,%9}, {%0,%1,%2,%3};"
        : "+f"(c[0]), "+f"(c[1]), "+f"(c[2]), "+f"(c[3])
        : "r"(__float_as_uint(a[0])), "r"(__float_as_uint(a[1])),
          "r"(__float_as_uint(a[2])), "r"(__float_as_uint(a[3])),
          "r"(__float_as_uint(b0)),  "r"(__float_as_uint(b1)));
}

__device__ __forceinline__ void stage128(float* dst, const float* __restrict__ src, int t) {
    const float4* g = (const float4*)src;
    #pragma unroll
    for (int r = 0; r < 16; r++) {
        int idx = r * 256 + t;
        float4 v = g[idx];
        int row = idx >> 5, col = (idx & 31) * 4;
        float* d = dst + row * 132 + col;
        d[0] = tf32r(v.x); d[1] = tf32r(v.y); d[2] = tf32r(v.z); d[3] = tf32r(v.w);
    }
}

// ------------------------- device scratch ---------------
__device__ float g_q [B_TOT*NH*LN*HD];
__device__ float g_k [B_TOT*NH*LN*HD];
__device__ float g_v [B_TOT*NH*LN*HD];
__device__ float g_oh[B_TOT*LN*CDIM];

// =============================================================================
// K1 (warp-MMA tf32) — unchanged from passing R8.
// =============================================================================
__global__ __launch_bounds__(256) void qkv_mma(const float* __restrict__ x,
                                               const float* __restrict__ w,
                                               const float* __restrict__ bias) {
    extern __shared__ float sm[];
    float* xs = sm;
    float* ws = sm + 128*132;
    float* bs = sm + 3*128*132;
    const int b = blockIdx.x, t = threadIdx.x;
    const int wid = t >> 5, lane = t & 31;
    const int gr = lane >> 2, tc = lane & 3;
    const int mrow = (wid & 3) * 32;
    const int n0b  = (wid >> 2) * 64;

    stage128(xs, x + (size_t)b * 16384, t);
    stage128(ws,             w,         t);
    stage128(ws + 128*132,   w + 16384, t);
    for (int idx = t; idx < 384; idx += 256) bs[idx] = bias[idx];
    __syncthreads();

    float a[2][16][4];
    #pragma unroll
    for (int mt = 0; mt < 2; mt++) {
        int r0 = mrow + mt * 16 + gr;
        #pragma unroll
        for (int ks = 0; ks < 16; ks++) {
            a[mt][ks][0] = xs[ r0      * 132 + ks*8 + tc];
            a[mt][ks][1] = xs[(r0 + 8) * 132 + ks*8 + tc];
            a[mt][ks][2] = xs[ r0      * 132 + ks*8 + tc + 4];
            a[mt][ks][3] = xs[(r0 + 8) * 132 + ks*8 + tc + 4];
        }
    }

    for (int cc = 0; cc < 3; cc++) {
        if (cc == 2) {
            __syncthreads();
            stage128(ws, w + 32768, t);
            __syncthreads();
        }
        const float* wc = ws + (cc & 1) * (128*132);
        float* arr = (cc == 0) ? g_q : ((cc == 1) ? g_k : g_v);
        const float scl = (cc == 0) ? SCALEF : 1.0f;
        #pragma unroll
        for (int nt = 0; nt < 8; nt++) {
            int n0 = n0b + nt * 8;
            float c0[4] = {0.f,0.f,0.f,0.f};
            float c1[4] = {0.f,0.f,0.f,0.f};
            #pragma unroll
            for (int ks = 0; ks < 16; ks++) {
                float b0 = wc[(n0 + gr) * 132 + ks*8 + tc];
                float b1 = wc[(n0 + gr) * 132 + ks*8 + tc + 4];
                mma8(c0, a[0][ks], b0, b1);
                mma8(c1, a[1][ks], b0, b1);
            }
            int cch = n0 + 2 * tc;
            float bb0 = bs[cc*128 + cch], bb1 = bs[cc*128 + cch + 1];
            int h = cch >> 5, ch = cch & 31;
            float* base = arr + (((size_t)b * NH + h) * LN) * HD + ch;
            #pragma unroll
            for (int mt = 0; mt < 2; mt++) {
                float* cr = mt ? c1 : c0;
                int r0 = mrow + mt * 16 + gr;
                *(float2*)(base +  r0      * HD) = make_float2((cr[0]+bb0)*scl, (cr[1]+bb1)*scl);
                *(float2*)(base + (r0 + 8) * HD) = make_float2((cr[2]+bb0)*scl, (cr[3]+bb1)*scl);
            }
        }
    }
}

// =============================================================================
// K2 v2: RPE via tf32 MMA GEMMs. Table fix vs R9: QR uses k_rpe (+32),
// KR uses q_rpe (+0, scaled).
// =============================================================================
__global__ __launch_bounds__(512, 1) void attn_kernel(const float* __restrict__ mask,
                                                      const float* __restrict__ rpe) {
    extern __shared__ float sm[];
    float* k_s  = sm;              // stride 36
    float* v_s  = sm + 4608;       // stride 32
    float* scr  = sm + 8704;       // stride 232 (Q-stage/QR/KR/W/bufs)
    float* tabb = sm + 38400;      // tabk/tabq [232][36]; tabvT [32][229]
    float* o2b  = sm + 46752;      // [128][36]
    float* redm = sm + 51360;
    float* reds = sm + 51872;
    float* buf0 = scr;             // alias (after O2 GEMM)
    float* buf1 = scr + 4608;

    const int b = blockIdx.x, h = blockIdx.y;
    const int t  = threadIdx.x;
    const int i  = t & 127;
    const int jq = t >> 7;
    const int wid = t >> 5, lane = t & 31;
    const int gr = lane >> 2, tc = lane & 3;

    // ---- S0: stage everything ----
    {
        const float4* kg = (const float4*)(g_k + (((size_t)b*NH + h)*LN)*HD);
        const float4* qg = (const float4*)(g_q + (((size_t)b*NH + h)*LN)*HD);
        const float4* vg = (const float4*)(g_v + (((size_t)b*NH + h)*LN)*HD);
        float4* v4 = (float4*)v_s;
        #pragma unroll
        for (int r = 0; r < 2; r++) {
            int idx4 = r*512 + t;
            float4 kv = kg[idx4], qv4 = qg[idx4];
            int row = idx4 >> 3, c4 = (idx4 & 7) * 4;
            float4 kt, qt;
            kt.x=tf32r(kv.x); kt.y=tf32r(kv.y); kt.z=tf32r(kv.z); kt.w=tf32r(kv.w);
            qt.x=tf32r(qv4.x); qt.y=tf32r(qv4.y); qt.z=tf32r(qv4.z); qt.w=tf32r(qv4.w);
            *(float4*)(k_s + row*36 + c4) = kt;
            *(float4*)(scr + row*36 + c4) = qt;
            v4[idx4] = vg[idx4];
        }
    }
    for (int idx = t; idx < 7200; idx += 512) {
        int r = idx >> 5, c = idx & 31;
        tabb[r*36 + c] = tf32r(rpe[r*384 + h*96 + 32 + c]);      // k_rpe (QR table)
    }
    if (t < 252) tabb[8100 + t] = 0.f;                           // zero rows 225..231
    // q regs (raw) + mask -> att
    ull qv[16];
    {
        const ulonglong2* qg = (const ulonglong2*)(g_q + (((size_t)b*NH + h)*LN + i)*HD);
        #pragma unroll
        for (int u = 0; u < 8; u++) { ulonglong2 z = qg[u]; qv[2*u] = z.x; qv[2*u+1] = z.y; }
    }
    float att[32];
    {
        const float4* mp = (const float4*)(mask + (size_t)(b & 127)*LN*LN + i*LN + jq*32);
        #pragma unroll
        for (int u = 0; u < 8; u++) {
            float4 m4 = mp[u];
            att[u*4+0] = m4.x; att[u*4+1] = m4.y; att[u*4+2] = m4.z; att[u*4+3] = m4.w;
        }
    }
    __syncthreads();

    const int hi = i >> 4;
    const int wi = (i >> 1) & 7;

    // ---- S1: qk (broadcast f32x2) + Q A-frags ----
    #pragma unroll
    for (int jj = 0; jj < 16; jj++) {
        int pj = jq*16 + jj;
        const ulonglong2* k0p = (const ulonglong2*)(k_s + pj*2*36);
        const ulonglong2* k1p = k0p + 9;
        ull qk0 = 0, qk1 = 0;
        #pragma unroll
        for (int u = 0; u < 8; u++) {
            ulonglong2 kv0 = k0p[u], kv1 = k1p[u];
            ull q0 = qv[2*u], q1 = qv[2*u+1];
            fma2(qk0, q0, kv0.x); fma2(qk0, q1, kv0.y);
            fma2(qk1, q0, kv1.x); fma2(qk1, q1, kv1.y);
        }
        float2 f0 = up2(qk0), f1 = up2(qk1);
        att[2*jj]   += f0.x + f0.y;
        att[2*jj+1] += f1.x + f1.y;
    }
    float fa[4][4];
    const int r0w = (wid & 7) * 16;
    if (wid < 8) {
        #pragma unroll
        for (int ks = 0; ks < 4; ks++) {
            fa[ks][0] = scr[(r0w + gr)     * 36 + ks*8 + tc];
            fa[ks][1] = scr[(r0w + gr + 8) * 36 + ks*8 + tc];
            fa[ks][2] = scr[(r0w + gr)     * 36 + ks*8 + tc + 4];
            fa[ks][3] = scr[(r0w + gr + 8) * 36 + ks*8 + tc + 4];
        }
    }
    __syncthreads();

    // ---- S2: QR GEMM -> scr ----
    if (wid < 8) {
        #pragma unroll
        for (int nt = 0; nt < 29; nt++) {
            float c4[4] = {0.f,0.f,0.f,0.f};
            #pragma unroll
            for (int ks = 0; ks < 4; ks++) {
                float b0 = tabb[(nt*8 + gr)*36 + ks*8 + tc];
                float b1 = tabb[(nt*8 + gr)*36 + ks*8 + tc + 4];
                mma8(c4, fa[ks], b0, b1);
            }
            *(float2*)(scr + (r0w + gr)    *232 + nt*8 + 2*tc) = make_float2(c4[0], c4[1]);
            *(float2*)(scr + (r0w + gr + 8)*232 + nt*8 + 2*tc) = make_float2(c4[2], c4[3]);
        }
    }
    __syncthreads();

    // ---- S3: gather QR; stage tabq (q_rpe * scale); K A-frags ----
    #pragma unroll
    for (int jj = 0; jj < 16; jj++) {
        int pj = jq*16 + jj;
        int ridx = (hi - (pj >> 3) + 7)*15 + (wi - (pj & 7) + 7);
        float qr = scr[i*232 + ridx];
        att[2*jj] += qr; att[2*jj+1] += qr;
    }
    __syncthreads();                       // QR reads done before scr overwrite
    for (int idx = t; idx < 7200; idx += 512) {
        int r = idx >> 5, c = idx & 31;
        tabb[r*36 + c] = tf32r(rpe[r*384 + h*96 + c] * SCALEF);  // q_rpe * scale (KR table)
    }
    if (wid < 8) {
        #pragma unroll
        for (int ks = 0; ks < 4; ks++) {
            fa[ks][0] = k_s[(r0w + gr)     * 36 + ks*8 + tc];
            fa[ks][1] = k_s[(r0w + gr + 8) * 36 + ks*8 + tc];
            fa[ks][2] = k_s[(r0w + gr)     * 36 + ks*8 + tc + 4];
            fa[ks][3] = k_s[(r0w + gr + 8) * 36 + ks*8 + tc + 4];
        }
    }
    __syncthreads();

    // ---- S4: KR GEMM -> scr ----
    if (wid < 8) {
        #pragma unroll
        for (int nt = 0; nt < 29; nt++) {
            float c4[4] = {0.f,0.f,0.f,0.f};
            #pragma unroll
            for (int ks = 0; ks < 4; ks++) {
                float b0 = tabb[(nt*8 + gr)*36 + ks*8 + tc];
                float b1 = tabb[(nt*8 + gr)*36 + ks*8 + tc + 4];
                mma8(c4, fa[ks], b0, b1);
            }
            *(float2*)(scr + (r0w + gr)    *232 + nt*8 + 2*tc) = make_float2(c4[0], c4[1]);
            *(float2*)(scr + (r0w + gr + 8)*232 + nt*8 + 2*tc) = make_float2(c4[2], c4[3]);
        }
    }
    __syncthreads();

    // ---- S5: gather KR ----
    #pragma unroll
    for (int jj = 0; jj < 16; jj++) {
        int pj = jq*16 + jj;
        int ridx = (hi - (pj >> 3) + 7)*15 + (wi - (pj & 7) + 7);
        att[2*jj]   += scr[(2*pj)    *232 + ridx];
        att[2*jj+1] += scr[(2*pj + 1)*232 + ridx];
    }

    // ---- S6: softmax ----
    float m = att[0];
    #pragma unroll
    for (int u = 1; u < 32; u++) m = fmaxf(m, att[u]);
    redm[jq*128 + i] = m;
    __syncthreads();
    m = fmaxf(fmaxf(redm[i], redm[128 + i]), fmaxf(redm[256 + i], redm[384 + i]));
    float ls = 0.f;
    #pragma unroll
    for (int u = 0; u < 32; u++) { float e = __expf(att[u] - m); att[u] = e; ls += e; }
    reds[jq*128 + i] = ls;
    __syncthreads();
    float rinv = 1.0f / (reds[i] + reds[128 + i] + reds[256 + i] + reds[384 + i]);

    // ---- S7: zero scr, stage tabv^T ----
    {
        float4 z = make_float4(0.f, 0.f, 0.f, 0.f);
        float4* s4 = (float4*)scr;
        for (int idx = t; idx < 7424; idx += 512) s4[idx] = z;
    }
    for (int idx = t; idx < 7200; idx += 512) {
        int r = idx >> 5, c = idx & 31;
        tabb[c*229 + r] = tf32r(rpe[r*384 + h*96 + 64 + c]);   // tabv^T [32][229]
    }
    __syncthreads();

    // ---- S8: W scatter + O1 (P@V, broadcast f32x2) ----
    #pragma unroll
    for (int jj = 0; jj < 16; jj++) {
        int pj = jq*16 + jj;
        int ridx = (hi - (pj >> 3) + 7)*15 + (wi - (pj & 7) + 7);
        scr[i*232 + ridx] = tf32r(att[2*jj] + att[2*jj+1]);
    }
    ull acc2[16];
    #pragma unroll
    for (int u = 0; u < 16; u++) acc2[u] = 0ull;
    #pragma unroll
    for (int jj = 0; jj < 16; jj++) {
        int pj = jq*16 + jj;
        const ulonglong2* v0p = (const ulonglong2*)(v_s + pj*2*HD);
        const ulonglong2* v1p = v0p + 8;
        ull ap0 = pk2(att[2*jj], att[2*jj]), ap1 = pk2(att[2*jj+1], att[2*jj+1]);
        #pragma unroll
        for (int u = 0; u < 8; u++) {
            ulonglong2 vv0 = v0p[u], vv1 = v1p[u];
            fma2(acc2[2*u],   ap0, vv0.x); fma2(acc2[2*u+1], ap0, vv0.y);
            fma2(acc2[2*u],   ap1, vv1.x); fma2(acc2[2*u+1], ap1, vv1.y);
        }
    }
    float o[32];
    #pragma unroll
    for (int u = 0; u < 16; u++) {
        float2 f = up2(acc2[u]);
        o[2*u] = f.x * rinv; o[2*u+1] = f.y * rinv;
    }
    __syncthreads();

    // ---- S9: O2 = W @ tabv -> o2b ----
    if (wid < 8) {
        float c16[16];
        #pragma unroll
        for (int u = 0; u < 16; u++) c16[u] = 0.f;
        for (int ks = 0; ks < 29; ks++) {
            float wa[4];
            wa[0] = scr[(r0w + gr)     *232 + ks*8 + tc];
            wa[1] = scr[(r0w + gr + 8) *232 + ks*8 + tc];
            wa[2] = scr[(r0w + gr)     *232 + ks*8 + tc + 4];
            wa[3] = scr[(r0w + gr + 8) *232 + ks*8 + tc + 4];
            #pragma unroll
            for (int nt = 0; nt < 4; nt++) {
                float b0 = tabb[(nt*8 + gr)*229 + ks*8 + tc];
                float b1 = tabb[(nt*8 + gr)*229 + ks*8 + tc + 4];
                mma8(c16 + nt*4, wa, b0, b1);
            }
        }
        #pragma unroll
        for (int nt = 0; nt < 4; nt++) {
            *(float2*)(o2b + (r0w + gr)    *36 + nt*8 + 2*tc) = make_float2(c16[nt*4+0], c16[nt*4+1]);
            *(float2*)(o2b + (r0w + gr + 8)*36 + nt*8 + 2*tc) = make_float2(c16[nt*4+2], c16[nt*4+3]);
        }
    }
    __syncthreads();

    // ---- S10: cross-jq reduce + add O2, store ----
    if (jq == 2) {
        for (int c = 0; c < 8; c++) *(float4*)(buf0 + i*36 + c*4) = *(float4*)(o + c*4);
    }
    if (jq == 3) {
        for (int c = 0; c < 8; c++) *(float4*)(buf1 + i*36 + c*4) = *(float4*)(o + c*4);
    }
    __syncthreads();
    if (jq == 0) {
        for (int c = 0; c < 32; c++) o[c] += buf0[i*36 + c];
    }
    if (jq == 1) {
        for (int c = 0; c < 32; c++) o[c] += buf1[i*36 + c];
    }
    __syncthreads();
    if (jq == 1) {
        for (int c = 0; c < 8; c++) *(float4*)(buf0 + i*36 + c*4) = *(float4*)(o + c*4);
    }
    __syncthreads();
    if (jq == 0) {
        float* dst = g_oh + ((size_t)b*LN + i)*CDIM + h*HD;
        #pragma unroll
        for (int c = 0; c < 8; c++) {
            float4 v;
            v.x = o[c*4+0] + buf0[i*36 + c*4+0] + o2b[i*36 + c*4+0] * rinv;
            v.y = o[c*4+1] + buf0[i*36 + c*4+1] + o2b[i*36 + c*4+1] * rinv;
            v.z = o[c*4+2] + buf0[i*36 + c*4+2] + o2b[i*36 + c*4+2] * rinv;
            v.w = o[c*4+3] + buf0[i*36 + c*4+3] + o2b[i*36 + c*4+3] * rinv;
            *(float4*)dst = v; dst += 4;
        }
    }
}

// =============================================================================
// K3 (warp-MMA tf32) — unchanged from passing R8.
// =============================================================================
__global__ __launch_bounds__(256) void proj_mma(const float* __restrict__ w,
                                                const float* __restrict__ bias,
                                                float* __restrict__ out) {
    extern __shared__ float sm[];
    float* xs = sm;
    float* ws = sm + 128*132;
    float* bs = sm + 2*128*132;
    const int b = blockIdx.x, t = threadIdx.x;
    const int wid = t >> 5, lane = t & 31;
    const int gr = lane >> 2, tc = lane & 3;
    const int mrow = (wid & 3) * 32;
    const int n0b  = (wid >> 2) * 64;

    stage128(xs, g_oh + (size_t)b * 16384, t);
    stage128(ws, w, t);
    if (t < 128) bs[t] = bias[t];
    __syncthreads();

    float a[2][16][4];
    #pragma unroll
    for (int mt = 0; mt < 2; mt++) {
        int r0 = mrow + mt * 16 + gr;
        #pragma unroll
        for (int ks = 0; ks < 16; ks++) {
            a[mt][ks][0] = xs[ r0      * 132 + ks*8 + tc];
            a[mt][ks][1] = xs[(r0 + 8) * 132 + ks*8 + tc];
            a[mt][ks][2] = xs[ r0      * 132 + ks*8 + tc + 4];
            a[mt][ks][3] = xs[(r0 + 8) * 132 + ks*8 + tc + 4];
        }
    }

    #pragma unroll
    for (int nt = 0; nt < 8; nt++) {
        int n0 = n0b + nt * 8;
        float c0[4] = {0.f,0.f,0.f,0.f};
        float c1[4] = {0.f,0.f,0.f,0.f};
        #pragma unroll
        for (int ks = 0; ks < 16; ks++) {
            float b0 = ws[(n0 + gr) * 132 + ks*8 + tc];
            float b1 = ws[(n0 + gr) * 132 + ks*8 + tc + 4];
            mma8(c0, a[0][ks], b0, b1);
            mma8(c1, a[1][ks], b0, b1);
        }
        int cch = n0 + 2 * tc;
        float bb0 = bs[cch], bb1 = bs[cch + 1];
        float* base = out + ((size_t)b * LN) * CDIM + cch;
        #pragma unroll
        for (int mt = 0; mt < 2; mt++) {
            float* cr = mt ? c1 : c0;
            int r0 = mrow + mt * 16 + gr;
            *(float2*)(base +  r0      * CDIM) = make_float2(cr[0] + bb0, cr[1] + bb1);
            *(float2*)(base + (r0 + 8) * CDIM) = make_float2(cr[2] + bb0, cr[3] + bb1);
        }
    }
}

// =============================================================================
extern "C" void kernel_launch(void* const* d_in, const int* in_sizes, int n_in,
                              void* d_out, int out_size) {
    const float* x        = (const float*)d_in[0];
    const float* attn_msk = (const float*)d_in[1];
    const float* qkv_w    = (const float*)d_in[2];
    const float* qkv_b    = (const float*)d_in[3];
    const float* rpe      = (const float*)d_in[4];
    const float* proj_w   = (const float*)d_in[5];
    const float* proj_b   = (const float*)d_in[6];
    float* out = (float*)d_out;

    const int smem_k1   = (3*128*132 + 384) * sizeof(float);   // 204288
    const int smem_attn = 52384 * sizeof(float);               // 209536
    const int smem_k3   = (2*128*132 + 128) * sizeof(float);   // 135680

    cudaFuncSetAttribute(qkv_mma,     cudaFuncAttributeMaxDynamicSharedMemorySize, smem_k1);
    cudaFuncSetAttribute(attn_kernel, cudaFuncAttributeMaxDynamicSharedMemorySize, smem_attn);
    cudaFuncSetAttribute(proj_mma,    cudaFuncAttributeMaxDynamicSharedMemorySize, smem_k3);

    qkv_mma <<<B_TOT, 256, smem_k1>>>(x, qkv_w, qkv_b);
    attn_kernel<<<dim3(B_TOT, NH), 512, smem_attn>>>(attn_msk, rpe);
    proj_mma<<<B_TOT, 256, smem_k3>>>(proj_w, proj_b, out);
}

// round 11
// speedup vs baseline: 1.1287x; 1.1287x over previous
#include <cuda_runtime.h>
#include <cstdint>

#define B_TOT 2048
#define LN    128
#define CDIM  128
#define NH    4
#define HD    32
#define SCALEF 0.17677669529663687f   // 32^-0.5

typedef unsigned long long ull;

// ---------- f32x2 packed helpers ----------
__device__ __forceinline__ void fma2(ull& d, ull a, ull b) {
    asm("fma.rn.f32x2 %0, %1, %2, %0;" : "+l"(d) : "l"(a), "l"(b));
}
__device__ __forceinline__ ull pk2(float x, float y) {
    ull r; asm("mov.b64 %0, {%1, %2};" : "=l"(r) : "f"(x), "f"(y)); return r;
}
__device__ __forceinline__ float2 up2(ull u) {
    float2 f; asm("mov.b64 {%0, %1}, %2;" : "=f"(f.x), "=f"(f.y) : "l"(u)); return f;
}

// ---------- tf32 warp MMA ----------
__device__ __forceinline__ float tf32r(float f) {
    uint32_t u; asm("cvt.rna.tf32.f32 %0, %1;" : "=r"(u) : "f"(f));
    return __uint_as_float(u);
}
__device__ __forceinline__ void mma8(float* c, const float* a, float b0, float b1) {
    asm volatile(
        "mma.sync.aligned.m16n8k8.row.col.f32.tf32.tf32.f32 "
        "{%0,%1,%2,%3}, {%4,%5,%6,%7}, {%8,%9}, {%0,%1,%2,%3};"
        : "+f"(c[0]), "+f"(c[1]), "+f"(c[2]), "+f"(c[3])
        : "r"(__float_as_uint(a[0])), "r"(__float_as_uint(a[1])),
          "r"(__float_as_uint(a[2])), "r"(__float_as_uint(a[3])),
          "r"(__float_as_uint(b0)),  "r"(__float_as_uint(b1)));
}

__device__ __forceinline__ void stage128(float* dst, const float* __restrict__ src, int t) {
    const float4* g = (const float4*)src;
    #pragma unroll
    for (int r = 0; r < 16; r++) {
        int idx = r * 256 + t;
        float4 v = g[idx];
        int row = idx >> 5, col = (idx & 31) * 4;
        float* d = dst + row * 132 + col;
        d[0] = tf32r(v.x); d[1] = tf32r(v.y); d[2] = tf32r(v.z); d[3] = tf32r(v.w);
    }
}

// ------------------------- device scratch ---------------
__device__ float g_q [B_TOT*NH*LN*HD];
__device__ float g_k [B_TOT*NH*LN*HD];
__device__ float g_v [B_TOT*NH*LN*HD];
__device__ float g_oh[B_TOT*LN*CDIM];

// =============================================================================
// K1 (warp-MMA tf32, ks-outer): qkv = x @ qkv_w.T + qkv_b.
// 16 live accumulator chains per warp (8 nt x 2 mt) to hide mma latency.
// =============================================================================
__global__ __launch_bounds__(256) void qkv_mma(const float* __restrict__ x,
                                               const float* __restrict__ w,
                                               const float* __restrict__ bias) {
    extern __shared__ float sm[];
    float* xs = sm;
    float* ws = sm + 128*132;
    float* bs = sm + 3*128*132;
    const int b = blockIdx.x, t = threadIdx.x;
    const int wid = t >> 5, lane = t & 31;
    const int gr = lane >> 2, tc = lane & 3;
    const int mrow = (wid & 3) * 32;
    const int n0b  = (wid >> 2) * 64;

    stage128(xs, x + (size_t)b * 16384, t);
    stage128(ws,             w,         t);
    stage128(ws + 128*132,   w + 16384, t);
    for (int idx = t; idx < 384; idx += 256) bs[idx] = bias[idx];
    __syncthreads();

    for (int cc = 0; cc < 3; cc++) {
        if (cc == 2) {
            __syncthreads();
            stage128(ws, w + 32768, t);
            __syncthreads();
        }
        const float* wc = ws + (cc & 1) * (128*132);
        float* arr = (cc == 0) ? g_q : ((cc == 1) ? g_k : g_v);
        const float scl = (cc == 0) ? SCALEF : 1.0f;

        float c[8][8];                    // [nt][mt0:0-3, mt1:4-7]
        #pragma unroll
        for (int nt = 0; nt < 8; nt++) {
            #pragma unroll
            for (int u = 0; u < 8; u++) c[nt][u] = 0.f;
        }

        #pragma unroll
        for (int ks = 0; ks < 16; ks++) {
            float a0[4], a1[4];
            a0[0] = xs[(mrow + gr)      * 132 + ks*8 + tc];
            a0[1] = xs[(mrow + gr + 8)  * 132 + ks*8 + tc];
            a0[2] = xs[(mrow + gr)      * 132 + ks*8 + tc + 4];
            a0[3] = xs[(mrow + gr + 8)  * 132 + ks*8 + tc + 4];
            a1[0] = xs[(mrow + gr + 16) * 132 + ks*8 + tc];
            a1[1] = xs[(mrow + gr + 24) * 132 + ks*8 + tc];
            a1[2] = xs[(mrow + gr + 16) * 132 + ks*8 + tc + 4];
            a1[3] = xs[(mrow + gr + 24) * 132 + ks*8 + tc + 4];
            #pragma unroll
            for (int nt = 0; nt < 8; nt++) {
                float b0 = wc[(n0b + nt*8 + gr) * 132 + ks*8 + tc];
                float b1 = wc[(n0b + nt*8 + gr) * 132 + ks*8 + tc + 4];
                mma8(c[nt],     a0, b0, b1);
                mma8(c[nt] + 4, a1, b0, b1);
            }
        }

        #pragma unroll
        for (int nt = 0; nt < 8; nt++) {
            int cch = n0b + nt*8 + 2*tc;
            float bb0 = bs[cc*128 + cch], bb1 = bs[cc*128 + cch + 1];
            int h = cch >> 5, ch = cch & 31;
            float* base = arr + (((size_t)b * NH + h) * LN) * HD + ch;
            #pragma unroll
            for (int mt = 0; mt < 2; mt++) {
                float* cr = c[nt] + mt*4;
                int r0 = mrow + mt * 16 + gr;
                *(float2*)(base +  r0      * HD) = make_float2((cr[0]+bb0)*scl, (cr[1]+bb1)*scl);
                *(float2*)(base + (r0 + 8) * HD) = make_float2((cr[2]+bb0)*scl, (cr[3]+bb1)*scl);
            }
        }
    }
}

// =============================================================================
// K2: fused attention per (b, h) — exact revert to the passing R8 version.
// =============================================================================
__global__ __launch_bounds__(512, 1) void attn_kernel(const float* __restrict__ mask,
                                                      const float* __restrict__ rpe) {
    extern __shared__ float sm[];
    float* k_s  = sm;                   // [128][32]
    float* v_s  = k_s + 4096;           // [128][32]
    float* tq   = v_s + 4096;           // [225][36] (scaled by SCALEF)
    float* tk   = tq  + 8100;           // [225][36]
    float* tv   = tk  + 8100;           // [225][36]
    float* buf0 = tv  + 8100;           // [128][36]
    float* buf1 = buf0 + 4608;          // [128][36]
    float* redm = buf1 + 4608;          // [512]
    float* reds = redm + 512;           // [512]

    const int b = blockIdx.x, h = blockIdx.y;
    const int t  = threadIdx.x;
    const int i  = t & 127;
    const int jq = t >> 7;

    {
        const float4* kg = (const float4*)(g_k + (((size_t)b*NH + h)*LN)*HD);
        const float4* vg = (const float4*)(g_v + (((size_t)b*NH + h)*LN)*HD);
        float4* k4 = (float4*)k_s;
        float4* v4 = (float4*)v_s;
        #pragma unroll
        for (int r = 0; r < 2; r++) { k4[r*512 + t] = kg[r*512 + t];
                                      v4[r*512 + t] = vg[r*512 + t]; }
    }
    for (int idx = t; idx < 225*96; idx += 512) {
        int tt = idx / 96;
        int u  = idx - tt*96;
        float val = rpe[tt*384 + h*96 + u];
        if      (u < 32) tq[tt*36 + u]      = val * SCALEF;
        else if (u < 64) tk[tt*36 + u - 32] = val;
        else             tv[tt*36 + u - 64] = val;
    }
    ull qv[16];
    {
        const ulonglong2* qg = (const ulonglong2*)(g_q + (((size_t)b*NH + h)*LN + i)*HD);
        #pragma unroll
        for (int u = 0; u < 8; u++) { ulonglong2 z = qg[u]; qv[2*u] = z.x; qv[2*u+1] = z.y; }
    }
    float att[32];
    {
        const float4* mp = (const float4*)(mask + (size_t)(b & 127)*LN*LN + i*LN + jq*32);
        #pragma unroll
        for (int u = 0; u < 8; u++) {
            float4 m4 = mp[u];
            att[u*4+0] = m4.x; att[u*4+1] = m4.y; att[u*4+2] = m4.z; att[u*4+3] = m4.w;
        }
    }
    __syncthreads();

    const int hi = i >> 4;
    const int wi = (i >> 1) & 7;

    #pragma unroll
    for (int jj = 0; jj < 16; jj++) {
        int pj = jq*16 + jj;
        int ridx = (hi - (pj >> 3) + 7)*15 + (wi - (pj & 7) + 7);
        const ulonglong2* k0p = (const ulonglong2*)(k_s + pj*2*HD);
        const ulonglong2* k1p = k0p + 8;
        const ulonglong2* tkp = (const ulonglong2*)(tk + ridx*36);
        const ulonglong2* tqp = (const ulonglong2*)(tq + ridx*36);
        ull qk0 = 0, qk1 = 0, qr = 0, kr0 = 0, kr1 = 0;
        #pragma unroll
        for (int u = 0; u < 8; u++) {
            ulonglong2 kv0 = k0p[u], kv1 = k1p[u], tkv = tkp[u], tqv = tqp[u];
            ull q0 = qv[2*u], q1 = qv[2*u+1];
            fma2(qk0, q0, kv0.x); fma2(qk0, q1, kv0.y);
            fma2(qk1, q0, kv1.x); fma2(qk1, q1, kv1.y);
            fma2(qr,  q0, tkv.x); fma2(qr,  q1, tkv.y);
            fma2(kr0, kv0.x, tqv.x); fma2(kr0, kv0.y, tqv.y);
            fma2(kr1, kv1.x, tqv.x); fma2(kr1, kv1.y, tqv.y);
        }
        float2 f0 = up2(qk0), f1 = up2(qk1), fr = up2(qr), g0 = up2(kr0), g1 = up2(kr1);
        float qrs = fr.x + fr.y;
        att[2*jj]   += f0.x + f0.y + qrs + g0.x + g0.y;
        att[2*jj+1] += f1.x + f1.y + qrs + g1.x + g1.y;
    }

    float m = att[0];
    #pragma unroll
    for (int u = 1; u < 32; u++) m = fmaxf(m, att[u]);
    redm[jq*128 + i] = m;
    __syncthreads();
    m = fmaxf(fmaxf(redm[i], redm[128 + i]), fmaxf(redm[256 + i], redm[384 + i]));
    float ls = 0.f;
    #pragma unroll
    for (int u = 0; u < 32; u++) { float e = __expf(att[u] - m); att[u] = e; ls += e; }
    reds[jq*128 + i] = ls;
    __syncthreads();
    float rinv = 1.0f / (reds[i] + reds[128 + i] + reds[256 + i] + reds[384 + i]);

    ull acc2[16];
    #pragma unroll
    for (int u = 0; u < 16; u++) acc2[u] = 0ull;

    #pragma unroll
    for (int jj = 0; jj < 16; jj++) {
        int pj = jq*16 + jj;
        int ridx = (hi - (pj >> 3) + 7)*15 + (wi - (pj & 7) + 7);
        const ulonglong2* v0p = (const ulonglong2*)(v_s + pj*2*HD);
        const ulonglong2* v1p = v0p + 8;
        const ulonglong2* tvp = (const ulonglong2*)(tv + ridx*36);
        float a0 = att[2*jj], a1 = att[2*jj+1];
        ull ap0 = pk2(a0, a0), ap1 = pk2(a1, a1), ap2 = pk2(a0 + a1, a0 + a1);
        #pragma unroll
        for (int u = 0; u < 8; u++) {
            ulonglong2 vv0 = v0p[u], vv1 = v1p[u], tvv = tvp[u];
            fma2(acc2[2*u],   ap0, vv0.x); fma2(acc2[2*u+1], ap0, vv0.y);
            fma2(acc2[2*u],   ap1, vv1.x); fma2(acc2[2*u+1], ap1, vv1.y);
            fma2(acc2[2*u],   ap2, tvv.x); fma2(acc2[2*u+1], ap2, tvv.y);
        }
    }

    float o[32];
    #pragma unroll
    for (int u = 0; u < 16; u++) {
        float2 f = up2(acc2[u]);
        o[2*u] = f.x * rinv; o[2*u+1] = f.y * rinv;
    }

    if (jq == 2) {
        for (int c = 0; c < 8; c++) *(float4*)(buf0 + i*36 + c*4) = *(float4*)(o + c*4);
    }
    if (jq == 3) {
        for (int c = 0; c < 8; c++) *(float4*)(buf1 + i*36 + c*4) = *(float4*)(o + c*4);
    }
    __syncthreads();
    if (jq == 0) {
        for (int c = 0; c < 32; c++) o[c] += buf0[i*36 + c];
    }
    if (jq == 1) {
        for (int c = 0; c < 32; c++) o[c] += buf1[i*36 + c];
    }
    __syncthreads();
    if (jq == 1) {
        for (int c = 0; c < 8; c++) *(float4*)(buf0 + i*36 + c*4) = *(float4*)(o + c*4);
    }
    __syncthreads();
    if (jq == 0) {
        float* dst = g_oh + ((size_t)b*LN + i)*CDIM + h*HD;
        #pragma unroll
        for (int c = 0; c < 8; c++) {
            float4 v;
            v.x = o[c*4+0] + buf0[i*36 + c*4+0];
            v.y = o[c*4+1] + buf0[i*36 + c*4+1];
            v.z = o[c*4+2] + buf0[i*36 + c*4+2];
            v.w = o[c*4+3] + buf0[i*36 + c*4+3];
            *(float4*)dst = v; dst += 4;
        }
    }
}

// =============================================================================
// K3 (warp-MMA tf32, ks-outer): out = oh @ proj_w.T + proj_b.
// =============================================================================
__global__ __launch_bounds__(256) void proj_mma(const float* __restrict__ w,
                                                const float* __restrict__ bias,
                                                float* __restrict__ out) {
    extern __shared__ float sm[];
    float* xs = sm;
    float* ws = sm + 128*132;
    float* bs = sm + 2*128*132;
    const int b = blockIdx.x, t = threadIdx.x;
    const int wid = t >> 5, lane = t & 31;
    const int gr = lane >> 2, tc = lane & 3;
    const int mrow = (wid & 3) * 32;
    const int n0b  = (wid >> 2) * 64;

    stage128(xs, g_oh + (size_t)b * 16384, t);
    stage128(ws, w, t);
    if (t < 128) bs[t] = bias[t];
    __syncthreads();

    float c[8][8];
    #pragma unroll
    for (int nt = 0; nt < 8; nt++) {
        #pragma unroll
        for (int u = 0; u < 8; u++) c[nt][u] = 0.f;
    }

    #pragma unroll
    for (int ks = 0; ks < 16; ks++) {
        float a0[4], a1[4];
        a0[0] = xs[(mrow + gr)      * 132 + ks*8 + tc];
        a0[1] = xs[(mrow + gr + 8)  * 132 + ks*8 + tc];
        a0[2] = xs[(mrow + gr)      * 132 + ks*8 + tc + 4];
        a0[3] = xs[(mrow + gr + 8)  * 132 + ks*8 + tc + 4];
        a1[0] = xs[(mrow + gr + 16) * 132 + ks*8 + tc];
        a1[1] = xs[(mrow + gr + 24) * 132 + ks*8 + tc];
        a1[2] = xs[(mrow + gr + 16) * 132 + ks*8 + tc + 4];
        a1[3] = xs[(mrow + gr + 24) * 132 + ks*8 + tc + 4];
        #pragma unroll
        for (int nt = 0; nt < 8; nt++) {
            float b0 = ws[(n0b + nt*8 + gr) * 132 + ks*8 + tc];
            float b1 = ws[(n0b + nt*8 + gr) * 132 + ks*8 + tc + 4];
            mma8(c[nt],     a0, b0, b1);
            mma8(c[nt] + 4, a1, b0, b1);
        }
    }

    #pragma unroll
    for (int nt = 0; nt < 8; nt++) {
        int cch = n0b + nt*8 + 2*tc;
        float bb0 = bs[cch], bb1 = bs[cch + 1];
        float* base = out + ((size_t)b * LN) * CDIM + cch;
        #pragma unroll
        for (int mt = 0; mt < 2; mt++) {
            float* cr = c[nt] + mt*4;
            int r0 = mrow + mt * 16 + gr;
            *(float2*)(base +  r0      * CDIM) = make_float2(cr[0] + bb0, cr[1] + bb1);
            *(float2*)(base + (r0 + 8) * CDIM) = make_float2(cr[2] + bb0, cr[3] + bb1);
        }
    }
}

// =============================================================================
extern "C" void kernel_launch(void* const* d_in, const int* in_sizes, int n_in,
                              void* d_out, int out_size) {
    const float* x        = (const float*)d_in[0];
    const float* attn_msk = (const float*)d_in[1];
    const float* qkv_w    = (const float*)d_in[2];
    const float* qkv_b    = (const float*)d_in[3];
    const float* rpe      = (const float*)d_in[4];
    const float* proj_w   = (const float*)d_in[5];
    const float* proj_b   = (const float*)d_in[6];
    float* out = (float*)d_out;

    const int smem_k1   = (3*128*132 + 384) * sizeof(float);                  // 204288
    const int smem_attn = (4096*2 + 3*8100 + 2*4608 + 1024) * sizeof(float);  // 170928
    const int smem_k3   = (2*128*132 + 128) * sizeof(float);                  // 135680

    cudaFuncSetAttribute(qkv_mma,     cudaFuncAttributeMaxDynamicSharedMemorySize, smem_k1);
    cudaFuncSetAttribute(attn_kernel, cudaFuncAttributeMaxDynamicSharedMemorySize, smem_attn);
    cudaFuncSetAttribute(proj_mma,    cudaFuncAttributeMaxDynamicSharedMemorySize, smem_k3);

    qkv_mma <<<B_TOT, 256, smem_k1>>>(x, qkv_w, qkv_b);
    attn_kernel<<<dim3(B_TOT, NH), 512, smem_attn>>>(attn_msk, rpe);
    proj_mma<<<B_TOT, 256, smem_k3>>>(proj_w, proj_b, out);
}

// round 12
// speedup vs baseline: 1.1445x; 1.0140x over previous
#include <cuda_runtime.h>
#include <cstdint>

#define B_TOT 2048
#define LN    128
#define CDIM  128
#define NH    4
#define HD    32
#define SCALEF 0.17677669529663687f   // 32^-0.5

typedef unsigned long long ull;

// ---------- f32x2 packed helpers ----------
__device__ __forceinline__ void fma2(ull& d, ull a, ull b) {
    asm("fma.rn.f32x2 %0, %1, %2, %0;" : "+l"(d) : "l"(a), "l"(b));
}
__device__ __forceinline__ ull pk2(float x, float y) {
    ull r; asm("mov.b64 %0, {%1, %2};" : "=l"(r) : "f"(x), "f"(y)); return r;
}
__device__ __forceinline__ float2 up2(ull u) {
    float2 f; asm("mov.b64 {%0, %1}, %2;" : "=f"(f.x), "=f"(f.y) : "l"(u)); return f;
}

// ---------- tf32 warp MMA ----------
__device__ __forceinline__ float tf32r(float f) {
    uint32_t u; asm("cvt.rna.tf32.f32 %0, %1;" : "=r"(u) : "f"(f));
    return __uint_as_float(u);
}
__device__ __forceinline__ void mma8(float* c, const float* a, float b0, float b1) {
    asm volatile(
        "mma.sync.aligned.m16n8k8.row.col.f32.tf32.tf32.f32 "
        "{%0,%1,%2,%3}, {%4,%5,%6,%7}, {%8,%9}, {%0,%1,%2,%3};"
        : "+f"(c[0]), "+f"(c[1]), "+f"(c[2]), "+f"(c[3])
        : "r"(__float_as_uint(a[0])), "r"(__float_as_uint(a[1])),
          "r"(__float_as_uint(a[2])), "r"(__float_as_uint(a[3])),
          "r"(__float_as_uint(b0)),  "r"(__float_as_uint(b1)));
}

// stage a 128x128 fp32 tile into smem stride-132 (tf32-rounded), 512 threads
__device__ __forceinline__ void stage128_512(float* dst, const float* __restrict__ src, int t) {
    const float4* g = (const float4*)src;
    #pragma unroll
    for (int r = 0; r < 8; r++) {
        int idx = r * 512 + t;            // 4096 float4 total
        float4 v = g[idx];
        int row = idx >> 5, col = (idx & 31) * 4;
        float* d = dst + row * 132 + col;
        d[0] = tf32r(v.x); d[1] = tf32r(v.y); d[2] = tf32r(v.z); d[3] = tf32r(v.w);
    }
}

// ------------------------- device scratch ---------------
__device__ float g_q [B_TOT*NH*LN*HD];
__device__ float g_k [B_TOT*NH*LN*HD];
__device__ float g_v [B_TOT*NH*LN*HD];
__device__ float g_oh[B_TOT*LN*CDIM];

// =============================================================================
// K1 (warp-MMA tf32, 2 windows/block): qkv = x @ qkv_w.T + qkv_b.
// 512 threads = 16 warps; warps 0-7 window A, 8-15 window B; weight chunk
// shared (single buffer, staged per cc).
// =============================================================================
__global__ __launch_bounds__(512) void qkv_mma(const float* __restrict__ x,
                                               const float* __restrict__ w,
                                               const float* __restrict__ bias) {
    extern __shared__ float sm[];
    float* xs = sm;                       // [2][128][132]
    float* ws = sm + 2*128*132;           // [128][132]
    float* bs = sm + 3*128*132;           // [384]
    const int t = threadIdx.x;
    const int wid = t >> 5, lane = t & 31;
    const int gr = lane >> 2, tc = lane & 3;
    const int w_i  = wid >> 3;            // window within block
    const int wid8 = wid & 7;
    const int mrow = (wid8 & 3) * 32;
    const int n0b  = (wid8 >> 2) * 64;
    const int b = blockIdx.x * 2 + w_i;
    float* xw = xs + w_i * (128*132);

    stage128_512(xs,           x + (size_t)(blockIdx.x*2)     * 16384, t);
    stage128_512(xs + 128*132, x + (size_t)(blockIdx.x*2 + 1) * 16384, t);
    if (t < 384) bs[t] = bias[t];

    for (int cc = 0; cc < 3; cc++) {
        __syncthreads();
        stage128_512(ws, w + cc * 16384, t);
        __syncthreads();

        float* arr = (cc == 0) ? g_q : ((cc == 1) ? g_k : g_v);
        const float scl = (cc == 0) ? SCALEF : 1.0f;

        float c[8][8];
        #pragma unroll
        for (int nt = 0; nt < 8; nt++) {
            #pragma unroll
            for (int u = 0; u < 8; u++) c[nt][u] = 0.f;
        }

        #pragma unroll
        for (int ks = 0; ks < 16; ks++) {
            float a0[4], a1[4];
            a0[0] = xw[(mrow + gr)      * 132 + ks*8 + tc];
            a0[1] = xw[(mrow + gr + 8)  * 132 + ks*8 + tc];
            a0[2] = xw[(mrow + gr)      * 132 + ks*8 + tc + 4];
            a0[3] = xw[(mrow + gr + 8)  * 132 + ks*8 + tc + 4];
            a1[0] = xw[(mrow + gr + 16) * 132 + ks*8 + tc];
            a1[1] = xw[(mrow + gr + 24) * 132 + ks*8 + tc];
            a1[2] = xw[(mrow + gr + 16) * 132 + ks*8 + tc + 4];
            a1[3] = xw[(mrow + gr + 24) * 132 + ks*8 + tc + 4];
            #pragma unroll
            for (int nt = 0; nt < 8; nt++) {
                float b0 = ws[(n0b + nt*8 + gr) * 132 + ks*8 + tc];
                float b1 = ws[(n0b + nt*8 + gr) * 132 + ks*8 + tc + 4];
                mma8(c[nt],     a0, b0, b1);
                mma8(c[nt] + 4, a1, b0, b1);
            }
        }

        #pragma unroll
        for (int nt = 0; nt < 8; nt++) {
            int cch = n0b + nt*8 + 2*tc;
            float bb0 = bs[cc*128 + cch], bb1 = bs[cc*128 + cch + 1];
            int h = cch >> 5, ch = cch & 31;
            float* base = arr + (((size_t)b * NH + h) * LN) * HD + ch;
            #pragma unroll
            for (int mt = 0; mt < 2; mt++) {
                float* cr = c[nt] + mt*4;
                int r0 = mrow + mt * 16 + gr;
                *(float2*)(base +  r0      * HD) = make_float2((cr[0]+bb0)*scl, (cr[1]+bb1)*scl);
                *(float2*)(base + (r0 + 8) * HD) = make_float2((cr[2]+bb0)*scl, (cr[3]+bb1)*scl);
            }
        }
    }
}

// =============================================================================
// K2: fused attention per (b, h) — byte-identical to passing R11 version.
// =============================================================================
__global__ __launch_bounds__(512, 1) void attn_kernel(const float* __restrict__ mask,
                                                      const float* __restrict__ rpe) {
    extern __shared__ float sm[];
    float* k_s  = sm;                   // [128][32]
    float* v_s  = k_s + 4096;           // [128][32]
    float* tq   = v_s + 4096;           // [225][36] (scaled by SCALEF)
    float* tk   = tq  + 8100;           // [225][36]
    float* tv   = tk  + 8100;           // [225][36]
    float* buf0 = tv  + 8100;           // [128][36]
    float* buf1 = buf0 + 4608;          // [128][36]
    float* redm = buf1 + 4608;          // [512]
    float* reds = redm + 512;           // [512]

    const int b = blockIdx.x, h = blockIdx.y;
    const int t  = threadIdx.x;
    const int i  = t & 127;
    const int jq = t >> 7;

    {
        const float4* kg = (const float4*)(g_k + (((size_t)b*NH + h)*LN)*HD);
        const float4* vg = (const float4*)(g_v + (((size_t)b*NH + h)*LN)*HD);
        float4* k4 = (float4*)k_s;
        float4* v4 = (float4*)v_s;
        #pragma unroll
        for (int r = 0; r < 2; r++) { k4[r*512 + t] = kg[r*512 + t];
                                      v4[r*512 + t] = vg[r*512 + t]; }
    }
    for (int idx = t; idx < 225*96; idx += 512) {
        int tt = idx / 96;
        int u  = idx - tt*96;
        float val = rpe[tt*384 + h*96 + u];
        if      (u < 32) tq[tt*36 + u]      = val * SCALEF;
        else if (u < 64) tk[tt*36 + u - 32] = val;
        else             tv[tt*36 + u - 64] = val;
    }
    ull qv[16];
    {
        const ulonglong2* qg = (const ulonglong2*)(g_q + (((size_t)b*NH + h)*LN + i)*HD);
        #pragma unroll
        for (int u = 0; u < 8; u++) { ulonglong2 z = qg[u]; qv[2*u] = z.x; qv[2*u+1] = z.y; }
    }
    float att[32];
    {
        const float4* mp = (const float4*)(mask + (size_t)(b & 127)*LN*LN + i*LN + jq*32);
        #pragma unroll
        for (int u = 0; u < 8; u++) {
            float4 m4 = mp[u];
            att[u*4+0] = m4.x; att[u*4+1] = m4.y; att[u*4+2] = m4.z; att[u*4+3] = m4.w;
        }
    }
    __syncthreads();

    const int hi = i >> 4;
    const int wi = (i >> 1) & 7;

    #pragma unroll
    for (int jj = 0; jj < 16; jj++) {
        int pj = jq*16 + jj;
        int ridx = (hi - (pj >> 3) + 7)*15 + (wi - (pj & 7) + 7);
        const ulonglong2* k0p = (const ulonglong2*)(k_s + pj*2*HD);
        const ulonglong2* k1p = k0p + 8;
        const ulonglong2* tkp = (const ulonglong2*)(tk + ridx*36);
        const ulonglong2* tqp = (const ulonglong2*)(tq + ridx*36);
        ull qk0 = 0, qk1 = 0, qr = 0, kr0 = 0, kr1 = 0;
        #pragma unroll
        for (int u = 0; u < 8; u++) {
            ulonglong2 kv0 = k0p[u], kv1 = k1p[u], tkv = tkp[u], tqv = tqp[u];
            ull q0 = qv[2*u], q1 = qv[2*u+1];
            fma2(qk0, q0, kv0.x); fma2(qk0, q1, kv0.y);
            fma2(qk1, q0, kv1.x); fma2(qk1, q1, kv1.y);
            fma2(qr,  q0, tkv.x); fma2(qr,  q1, tkv.y);
            fma2(kr0, kv0.x, tqv.x); fma2(kr0, kv0.y, tqv.y);
            fma2(kr1, kv1.x, tqv.x); fma2(kr1, kv1.y, tqv.y);
        }
        float2 f0 = up2(qk0), f1 = up2(qk1), fr = up2(qr), g0 = up2(kr0), g1 = up2(kr1);
        float qrs = fr.x + fr.y;
        att[2*jj]   += f0.x + f0.y + qrs + g0.x + g0.y;
        att[2*jj+1] += f1.x + f1.y + qrs + g1.x + g1.y;
    }

    float m = att[0];
    #pragma unroll
    for (int u = 1; u < 32; u++) m = fmaxf(m, att[u]);
    redm[jq*128 + i] = m;
    __syncthreads();
    m = fmaxf(fmaxf(redm[i], redm[128 + i]), fmaxf(redm[256 + i], redm[384 + i]));
    float ls = 0.f;
    #pragma unroll
    for (int u = 0; u < 32; u++) { float e = __expf(att[u] - m); att[u] = e; ls += e; }
    reds[jq*128 + i] = ls;
    __syncthreads();
    float rinv = 1.0f / (reds[i] + reds[128 + i] + reds[256 + i] + reds[384 + i]);

    ull acc2[16];
    #pragma unroll
    for (int u = 0; u < 16; u++) acc2[u] = 0ull;

    #pragma unroll
    for (int jj = 0; jj < 16; jj++) {
        int pj = jq*16 + jj;
        int ridx = (hi - (pj >> 3) + 7)*15 + (wi - (pj & 7) + 7);
        const ulonglong2* v0p = (const ulonglong2*)(v_s + pj*2*HD);
        const ulonglong2* v1p = v0p + 8;
        const ulonglong2* tvp = (const ulonglong2*)(tv + ridx*36);
        float a0 = att[2*jj], a1 = att[2*jj+1];
        ull ap0 = pk2(a0, a0), ap1 = pk2(a1, a1), ap2 = pk2(a0 + a1, a0 + a1);
        #pragma unroll
        for (int u = 0; u < 8; u++) {
            ulonglong2 vv0 = v0p[u], vv1 = v1p[u], tvv = tvp[u];
            fma2(acc2[2*u],   ap0, vv0.x); fma2(acc2[2*u+1], ap0, vv0.y);
            fma2(acc2[2*u],   ap1, vv1.x); fma2(acc2[2*u+1], ap1, vv1.y);
            fma2(acc2[2*u],   ap2, tvv.x); fma2(acc2[2*u+1], ap2, tvv.y);
        }
    }

    float o[32];
    #pragma unroll
    for (int u = 0; u < 16; u++) {
        float2 f = up2(acc2[u]);
        o[2*u] = f.x * rinv; o[2*u+1] = f.y * rinv;
    }

    if (jq == 2) {
        for (int c = 0; c < 8; c++) *(float4*)(buf0 + i*36 + c*4) = *(float4*)(o + c*4);
    }
    if (jq == 3) {
        for (int c = 0; c < 8; c++) *(float4*)(buf1 + i*36 + c*4) = *(float4*)(o + c*4);
    }
    __syncthreads();
    if (jq == 0) {
        for (int c = 0; c < 32; c++) o[c] += buf0[i*36 + c];
    }
    if (jq == 1) {
        for (int c = 0; c < 32; c++) o[c] += buf1[i*36 + c];
    }
    __syncthreads();
    if (jq == 1) {
        for (int c = 0; c < 8; c++) *(float4*)(buf0 + i*36 + c*4) = *(float4*)(o + c*4);
    }
    __syncthreads();
    if (jq == 0) {
        float* dst = g_oh + ((size_t)b*LN + i)*CDIM + h*HD;
        #pragma unroll
        for (int c = 0; c < 8; c++) {
            float4 v;
            v.x = o[c*4+0] + buf0[i*36 + c*4+0];
            v.y = o[c*4+1] + buf0[i*36 + c*4+1];
            v.z = o[c*4+2] + buf0[i*36 + c*4+2];
            v.w = o[c*4+3] + buf0[i*36 + c*4+3];
            *(float4*)dst = v; dst += 4;
        }
    }
}

// =============================================================================
// K3 (warp-MMA tf32, 2 windows/block): out = oh @ proj_w.T + proj_b.
// =============================================================================
__global__ __launch_bounds__(512) void proj_mma(const float* __restrict__ w,
                                                const float* __restrict__ bias,
                                                float* __restrict__ out) {
    extern __shared__ float sm[];
    float* xs = sm;                       // [2][128][132]
    float* ws = sm + 2*128*132;           // [128][132]
    float* bs = sm + 3*128*132;           // [128]
    const int t = threadIdx.x;
    const int wid = t >> 5, lane = t & 31;
    const int gr = lane >> 2, tc = lane & 3;
    const int w_i  = wid >> 3;
    const int wid8 = wid & 7;
    const int mrow = (wid8 & 3) * 32;
    const int n0b  = (wid8 >> 2) * 64;
    const int b = blockIdx.x * 2 + w_i;
    float* xw = xs + w_i * (128*132);

    stage128_512(xs,           g_oh + (size_t)(blockIdx.x*2)     * 16384, t);
    stage128_512(xs + 128*132, g_oh + (size_t)(blockIdx.x*2 + 1) * 16384, t);
    stage128_512(ws, w, t);
    if (t < 128) bs[t] = bias[t];
    __syncthreads();

    float c[8][8];
    #pragma unroll
    for (int nt = 0; nt < 8; nt++) {
        #pragma unroll
        for (int u = 0; u < 8; u++) c[nt][u] = 0.f;
    }

    #pragma unroll
    for (int ks = 0; ks < 16; ks++) {
        float a0[4], a1[4];
        a0[0] = xw[(mrow + gr)      * 132 + ks*8 + tc];
        a0[1] = xw[(mrow + gr + 8)  * 132 + ks*8 + tc];
        a0[2] = xw[(mrow + gr)      * 132 + ks*8 + tc + 4];
        a0[3] = xw[(mrow + gr + 8)  * 132 + ks*8 + tc + 4];
        a1[0] = xw[(mrow + gr + 16) * 132 + ks*8 + tc];
        a1[1] = xw[(mrow + gr + 24) * 132 + ks*8 + tc];
        a1[2] = xw[(mrow + gr + 16) * 132 + ks*8 + tc + 4];
        a1[3] = xw[(mrow + gr + 24) * 132 + ks*8 + tc + 4];
        #pragma unroll
        for (int nt = 0; nt < 8; nt++) {
            float b0 = ws[(n0b + nt*8 + gr) * 132 + ks*8 + tc];
            float b1 = ws[(n0b + nt*8 + gr) * 132 + ks*8 + tc + 4];
            mma8(c[nt],     a0, b0, b1);
            mma8(c[nt] + 4, a1, b0, b1);
        }
    }

    #pragma unroll
    for (int nt = 0; nt < 8; nt++) {
        int cch = n0b + nt*8 + 2*tc;
        float bb0 = bs[cch], bb1 = bs[cch + 1];
        float* base = out + ((size_t)b * LN) * CDIM + cch;
        #pragma unroll
        for (int mt = 0; mt < 2; mt++) {
            float* cr = c[nt] + mt*4;
            int r0 = mrow + mt * 16 + gr;
            *(float2*)(base +  r0      * CDIM) = make_float2(cr[0] + bb0, cr[1] + bb1);
            *(float2*)(base + (r0 + 8) * CDIM) = make_float2(cr[2] + bb0, cr[3] + bb1);
        }
    }
}

// =============================================================================
extern "C" void kernel_launch(void* const* d_in, const int* in_sizes, int n_in,
                              void* d_out, int out_size) {
    const float* x        = (const float*)d_in[0];
    const float* attn_msk = (const float*)d_in[1];
    const float* qkv_w    = (const float*)d_in[2];
    const float* qkv_b    = (const float*)d_in[3];
    const float* rpe      = (const float*)d_in[4];
    const float* proj_w   = (const float*)d_in[5];
    const float* proj_b   = (const float*)d_in[6];
    float* out = (float*)d_out;

    const int smem_k1   = (3*128*132 + 384) * sizeof(float);                  // 204288
    const int smem_attn = (4096*2 + 3*8100 + 2*4608 + 1024) * sizeof(float);  // 170928
    const int smem_k3   = (3*128*132 + 128) * sizeof(float);                  // 203264

    cudaFuncSetAttribute(qkv_mma,     cudaFuncAttributeMaxDynamicSharedMemorySize, smem_k1);
    cudaFuncSetAttribute(attn_kernel, cudaFuncAttributeMaxDynamicSharedMemorySize, smem_attn);
    cudaFuncSetAttribute(proj_mma,    cudaFuncAttributeMaxDynamicSharedMemorySize, smem_k3);

    qkv_mma <<<B_TOT/2, 512, smem_k1>>>(x, qkv_w, qkv_b);
    attn_kernel<<<dim3(B_TOT, NH), 512, smem_attn>>>(attn_msk, rpe);
    proj_mma<<<B_TOT/2, 512, smem_k3>>>(proj_w, proj_b, out);
}

// round 13
// speedup vs baseline: 1.1446x; 1.0001x over previous
#include <cuda_runtime.h>
#include <cstdint>

#define B_TOT 2048
#define LN    128
#define CDIM  128
#define NH    4
#define HD    32
#define SCALEF 0.17677669529663687f   // 32^-0.5

typedef unsigned long long ull;

// ---------- f32x2 packed helpers ----------
__device__ __forceinline__ void fma2(ull& d, ull a, ull b) {
    asm("fma.rn.f32x2 %0, %1, %2, %0;" : "+l"(d) : "l"(a), "l"(b));
}
__device__ __forceinline__ ull pk2(float x, float y) {
    ull r; asm("mov.b64 %0, {%1, %2};" : "=l"(r) : "f"(x), "f"(y)); return r;
}
__device__ __forceinline__ float2 up2(ull u) {
    float2 f; asm("mov.b64 {%0, %1}, %2;" : "=f"(f.x), "=f"(f.y) : "l"(u)); return f;
}

// ---------- tf32 warp MMA ----------
__device__ __forceinline__ float tf32r(float f) {
    uint32_t u; asm("cvt.rna.tf32.f32 %0, %1;" : "=r"(u) : "f"(f));
    return __uint_as_float(u);
}
__device__ __forceinline__ void mma8(float* c, const float* a, float b0, float b1) {
    asm volatile(
        "mma.sync.aligned.m16n8k8.row.col.f32.tf32.tf32.f32 "
        "{%0,%1,%2,%3}, {%4,%5,%6,%7}, {%8,%9}, {%0,%1,%2,%3};"
        : "+f"(c[0]), "+f"(c[1]), "+f"(c[2]), "+f"(c[3])
        : "r"(__float_as_uint(a[0])), "r"(__float_as_uint(a[1])),
          "r"(__float_as_uint(a[2])), "r"(__float_as_uint(a[3])),
          "r"(__float_as_uint(b0)),  "r"(__float_as_uint(b1)));
}

// stage a 128x128 fp32 tile into smem stride-132 (tf32-rounded), 512 threads
__device__ __forceinline__ void stage128_512(float* dst, const float* __restrict__ src, int t) {
    const float4* g = (const float4*)src;
    #pragma unroll
    for (int r = 0; r < 8; r++) {
        int idx = r * 512 + t;            // 4096 float4 total
        float4 v = g[idx];
        int row = idx >> 5, col = (idx & 31) * 4;
        float* d = dst + row * 132 + col;
        d[0] = tf32r(v.x); d[1] = tf32r(v.y); d[2] = tf32r(v.z); d[3] = tf32r(v.w);
    }
}

// ------------------------- device scratch ---------------
__device__ float g_q [B_TOT*NH*LN*HD];
__device__ float g_k [B_TOT*NH*LN*HD];
__device__ float g_v [B_TOT*NH*LN*HD];
__device__ float g_oh[B_TOT*LN*CDIM];

// =============================================================================
// K1 (warp-MMA tf32, 2 windows/block) — unchanged from passing R12.
// =============================================================================
__global__ __launch_bounds__(512) void qkv_mma(const float* __restrict__ x,
                                               const float* __restrict__ w,
                                               const float* __restrict__ bias) {
    extern __shared__ float sm[];
    float* xs = sm;                       // [2][128][132]
    float* ws = sm + 2*128*132;           // [128][132]
    float* bs = sm + 3*128*132;           // [384]
    const int t = threadIdx.x;
    const int wid = t >> 5, lane = t & 31;
    const int gr = lane >> 2, tc = lane & 3;
    const int w_i  = wid >> 3;
    const int wid8 = wid & 7;
    const int mrow = (wid8 & 3) * 32;
    const int n0b  = (wid8 >> 2) * 64;
    const int b = blockIdx.x * 2 + w_i;
    float* xw = xs + w_i * (128*132);

    stage128_512(xs,           x + (size_t)(blockIdx.x*2)     * 16384, t);
    stage128_512(xs + 128*132, x + (size_t)(blockIdx.x*2 + 1) * 16384, t);
    if (t < 384) bs[t] = bias[t];

    for (int cc = 0; cc < 3; cc++) {
        __syncthreads();
        stage128_512(ws, w + cc * 16384, t);
        __syncthreads();

        float* arr = (cc == 0) ? g_q : ((cc == 1) ? g_k : g_v);
        const float scl = (cc == 0) ? SCALEF : 1.0f;

        float c[8][8];
        #pragma unroll
        for (int nt = 0; nt < 8; nt++) {
            #pragma unroll
            for (int u = 0; u < 8; u++) c[nt][u] = 0.f;
        }

        #pragma unroll
        for (int ks = 0; ks < 16; ks++) {
            float a0[4], a1[4];
            a0[0] = xw[(mrow + gr)      * 132 + ks*8 + tc];
            a0[1] = xw[(mrow + gr + 8)  * 132 + ks*8 + tc];
            a0[2] = xw[(mrow + gr)      * 132 + ks*8 + tc + 4];
            a0[3] = xw[(mrow + gr + 8)  * 132 + ks*8 + tc + 4];
            a1[0] = xw[(mrow + gr + 16) * 132 + ks*8 + tc];
            a1[1] = xw[(mrow + gr + 24) * 132 + ks*8 + tc];
            a1[2] = xw[(mrow + gr + 16) * 132 + ks*8 + tc + 4];
            a1[3] = xw[(mrow + gr + 24) * 132 + ks*8 + tc + 4];
            #pragma unroll
            for (int nt = 0; nt < 8; nt++) {
                float b0 = ws[(n0b + nt*8 + gr) * 132 + ks*8 + tc];
                float b1 = ws[(n0b + nt*8 + gr) * 132 + ks*8 + tc + 4];
                mma8(c[nt],     a0, b0, b1);
                mma8(c[nt] + 4, a1, b0, b1);
            }
        }

        #pragma unroll
        for (int nt = 0; nt < 8; nt++) {
            int cch = n0b + nt*8 + 2*tc;
            float bb0 = bs[cc*128 + cch], bb1 = bs[cc*128 + cch + 1];
            int h = cch >> 5, ch = cch & 31;
            float* base = arr + (((size_t)b * NH + h) * LN) * HD + ch;
            #pragma unroll
            for (int mt = 0; mt < 2; mt++) {
                float* cr = c[nt] + mt*4;
                int r0 = mrow + mt * 16 + gr;
                *(float2*)(base +  r0      * HD) = make_float2((cr[0]+bb0)*scl, (cr[1]+bb1)*scl);
                *(float2*)(base + (r0 + 8) * HD) = make_float2((cr[2]+bb0)*scl, (cr[3]+bb1)*scl);
            }
        }
    }
}

// =============================================================================
// K2 v3: qk + kr in f32x2 loops; qr and v_rpe-output via 16-warp band-reduced
// tf32 GEMMs (width 120 per m-strip, stride-122 scratch, lidx gathers).
// =============================================================================
__global__ __launch_bounds__(512, 1) void attn_kernel(const float* __restrict__ mask,
                                                      const float* __restrict__ rpe) {
    extern __shared__ float sm[];
    float* k_s  = sm;                   // [128][32]   raw k
    float* v_s  = sm + 4096;            // [128][32]   raw v
    float* q_s  = sm + 8192;            // [128][36]   tf32 q (scaled)
    float* tq   = sm + 12800;           // [225][36]   q_rpe * SCALEF (raw)
    float* tab  = sm + 20900;           // [232][36] tabk(tf32) -> [32][233] tabv^T(tf32)
    float* scr  = sm + 29252;           // [128][122]  QR -> W
    float* o2b  = sm + 44868;           // [128][36]
    float* redm = sm + 49476;           // [512]
    float* reds = sm + 49988;           // [512]
    float* buf0 = scr;                  // alias after O2 GEMM
    float* buf1 = scr + 4608;

    const int b = blockIdx.x, h = blockIdx.y;
    const int t  = threadIdx.x;
    const int i  = t & 127;
    const int jq = t >> 7;
    const int wid = t >> 5, lane = t & 31;
    const int gr = lane >> 2, tc = lane & 3;
    const int ms = wid & 7;             // m-strip (16 rows), hi of strip = ms
    const int nh = wid >> 3;            // n-half

    // ---- P0: stage k, v (raw), q (tf32), tq (scaled), tabk (tf32) ----
    {
        const float4* kg = (const float4*)(g_k + (((size_t)b*NH + h)*LN)*HD);
        const float4* vg = (const float4*)(g_v + (((size_t)b*NH + h)*LN)*HD);
        const float4* qg = (const float4*)(g_q + (((size_t)b*NH + h)*LN)*HD);
        float4* k4 = (float4*)k_s;
        float4* v4 = (float4*)v_s;
        #pragma unroll
        for (int r = 0; r < 2; r++) {
            int idx4 = r*512 + t;
            k4[idx4] = kg[idx4];
            v4[idx4] = vg[idx4];
            float4 qv4 = qg[idx4];
            int row = idx4 >> 3, c4 = (idx4 & 7) * 4;
            float* d = q_s + row*36 + c4;
            d[0] = tf32r(qv4.x); d[1] = tf32r(qv4.y);
            d[2] = tf32r(qv4.z); d[3] = tf32r(qv4.w);
        }
    }
    for (int idx = t; idx < 7200; idx += 512) {
        int tt = idx >> 5, u = idx & 31;
        tq[tt*36 + u]  = rpe[tt*384 + h*96 + u] * SCALEF;          // q_rpe * scale
        tab[tt*36 + u] = tf32r(rpe[tt*384 + h*96 + 32 + u]);       // k_rpe (QR table)
    }
    ull qv[16];
    {
        const ulonglong2* qg = (const ulonglong2*)(g_q + (((size_t)b*NH + h)*LN + i)*HD);
        #pragma unroll
        for (int u = 0; u < 8; u++) { ulonglong2 z = qg[u]; qv[2*u] = z.x; qv[2*u+1] = z.y; }
    }
    float att[32];
    {
        const float4* mp = (const float4*)(mask + (size_t)(b & 127)*LN*LN + i*LN + jq*32);
        #pragma unroll
        for (int u = 0; u < 8; u++) {
            float4 m4 = mp[u];
            att[u*4+0] = m4.x; att[u*4+1] = m4.y; att[u*4+2] = m4.z; att[u*4+3] = m4.w;
        }
    }
    __syncthreads();

    const int hi = i >> 4;
    const int wi = (i >> 1) & 7;

    // ---- P1: qk + kr (f32x2) ----
    #pragma unroll
    for (int jj = 0; jj < 16; jj++) {
        int pj = jq*16 + jj;
        int ridx = (hi - (pj >> 3) + 7)*15 + (wi - (pj & 7) + 7);
        const ulonglong2* k0p = (const ulonglong2*)(k_s + pj*2*HD);
        const ulonglong2* k1p = k0p + 8;
        const ulonglong2* tqp = (const ulonglong2*)(tq + ridx*36);
        ull qk0 = 0, qk1 = 0, kr0 = 0, kr1 = 0;
        #pragma unroll
        for (int u = 0; u < 8; u++) {
            ulonglong2 kv0 = k0p[u], kv1 = k1p[u], tqv = tqp[u];
            ull q0 = qv[2*u], q1 = qv[2*u+1];
            fma2(qk0, q0, kv0.x); fma2(qk0, q1, kv0.y);
            fma2(qk1, q0, kv1.x); fma2(qk1, q1, kv1.y);
            fma2(kr0, kv0.x, tqv.x); fma2(kr0, kv0.y, tqv.y);
            fma2(kr1, kv1.x, tqv.x); fma2(kr1, kv1.y, tqv.y);
        }
        float2 f0 = up2(qk0), f1 = up2(qk1), g0 = up2(kr0), g1 = up2(kr1);
        att[2*jj]   += f0.x + f0.y + g0.x + g0.y;
        att[2*jj+1] += f1.x + f1.y + g1.x + g1.y;
    }

    // ---- P2: QR GEMM (16 warps, band width 120 per m-strip) ----
    {
        float fa[4][4];
        #pragma unroll
        for (int ks = 0; ks < 4; ks++) {
            fa[ks][0] = q_s[(ms*16 + gr)     * 36 + ks*8 + tc];
            fa[ks][1] = q_s[(ms*16 + gr + 8) * 36 + ks*8 + tc];
            fa[ks][2] = q_s[(ms*16 + gr)     * 36 + ks*8 + tc + 4];
            fa[ks][3] = q_s[(ms*16 + gr + 8) * 36 + ks*8 + tc + 4];
        }
        const int ntmax = nh ? 7 : 8;
        for (int nt = 0; nt < ntmax; nt++) {
            float c4[4] = {0.f, 0.f, 0.f, 0.f};
            #pragma unroll
            for (int ks = 0; ks < 4; ks++) {
                int trow = ms*15 + nh*64 + nt*8 + gr;
                float b0 = tab[trow*36 + ks*8 + tc];
                float b1 = tab[trow*36 + ks*8 + tc + 4];
                mma8(c4, fa[ks], b0, b1);
            }
            int col = nh*64 + nt*8 + 2*tc;
            *(float2*)(scr + (ms*16 + gr)     * 122 + col) = make_float2(c4[0], c4[1]);
            *(float2*)(scr + (ms*16 + gr + 8) * 122 + col) = make_float2(c4[2], c4[3]);
        }
    }
    __syncthreads();

    // ---- P3: gather QR (band-local lidx) ----
    #pragma unroll
    for (int jj = 0; jj < 16; jj++) {
        int pj = jq*16 + jj;
        int lidx = (7 - (pj >> 3))*15 + (wi - (pj & 7) + 7);
        float qr = scr[i*122 + lidx];
        att[2*jj] += qr; att[2*jj+1] += qr;
    }

    // ---- softmax ----
    float m = att[0];
    #pragma unroll
    for (int u = 1; u < 32; u++) m = fmaxf(m, att[u]);
    redm[jq*128 + i] = m;
    __syncthreads();
    m = fmaxf(fmaxf(redm[i], redm[128 + i]), fmaxf(redm[256 + i], redm[384 + i]));
    float ls = 0.f;
    #pragma unroll
    for (int u = 0; u < 32; u++) { float e = __expf(att[u] - m); att[u] = e; ls += e; }
    reds[jq*128 + i] = ls;
    __syncthreads();
    float rinv = 1.0f / (reds[i] + reds[128 + i] + reds[256 + i] + reds[384 + i]);

    // ---- P4: zero W region; stage tabv^T [32][233] (tf32) ----
    {
        float4 z = make_float4(0.f, 0.f, 0.f, 0.f);
        float4* s4 = (float4*)scr;
        #pragma unroll
        for (int r = 0; r < 8; r++) {
            int idx = r*512 + t;
            if (idx < 3904) s4[idx] = z;     // 128*122/4
        }
    }
    for (int idx = t; idx < 7200; idx += 512) {
        int tt = idx >> 5, u = idx & 31;
        tab[u*233 + tt] = tf32r(rpe[tt*384 + h*96 + 64 + u]);      // v_rpe^T
    }
    __syncthreads();

    // ---- P5: scatter W (tf32, band-local) + O1 = P@V (f32x2) ----
    #pragma unroll
    for (int jj = 0; jj < 16; jj++) {
        int pj = jq*16 + jj;
        int lidx = (7 - (pj >> 3))*15 + (wi - (pj & 7) + 7);
        scr[i*122 + lidx] = tf32r(att[2*jj] + att[2*jj+1]);
    }
    ull acc2[16];
    #pragma unroll
    for (int u = 0; u < 16; u++) acc2[u] = 0ull;
    #pragma unroll
    for (int jj = 0; jj < 16; jj++) {
        int pj = jq*16 + jj;
        const ulonglong2* v0p = (const ulonglong2*)(v_s + pj*2*HD);
        const ulonglong2* v1p = v0p + 8;
        ull ap0 = pk2(att[2*jj], att[2*jj]), ap1 = pk2(att[2*jj+1], att[2*jj+1]);
        #pragma unroll
        for (int u = 0; u < 8; u++) {
            ulonglong2 vv0 = v0p[u], vv1 = v1p[u];
            fma2(acc2[2*u],   ap0, vv0.x); fma2(acc2[2*u+1], ap0, vv0.y);
            fma2(acc2[2*u],   ap1, vv1.x); fma2(acc2[2*u+1], ap1, vv1.y);
        }
    }
    float o[32];
    #pragma unroll
    for (int u = 0; u < 16; u++) {
        float2 f = up2(acc2[u]);
        o[2*u] = f.x * rinv; o[2*u+1] = f.y * rinv;
    }
    __syncthreads();

    // ---- P6: O2 = W @ tabv (band K=120 per m-strip) -> o2b ----
    {
        float c2[2][4];
        #pragma unroll
        for (int nt = 0; nt < 2; nt++) {
            #pragma unroll
            for (int u = 0; u < 4; u++) c2[nt][u] = 0.f;
        }
        for (int ks = 0; ks < 15; ks++) {
            float wa[4];
            wa[0] = scr[(ms*16 + gr)     * 122 + ks*8 + tc];
            wa[1] = scr[(ms*16 + gr + 8) * 122 + ks*8 + tc];
            wa[2] = scr[(ms*16 + gr)     * 122 + ks*8 + tc + 4];
            wa[3] = scr[(ms*16 + gr + 8) * 122 + ks*8 + tc + 4];
            #pragma unroll
            for (int nt = 0; nt < 2; nt++) {
                int crow = nh*16 + nt*8 + gr;
                float b0 = tab[crow*233 + ms*15 + ks*8 + tc];
                float b1 = tab[crow*233 + ms*15 + ks*8 + tc + 4];
                mma8(c2[nt], wa, b0, b1);
            }
        }
        #pragma unroll
        for (int nt = 0; nt < 2; nt++) {
            int col = nh*16 + nt*8 + 2*tc;
            *(float2*)(o2b + (ms*16 + gr)     * 36 + col) = make_float2(c2[nt][0], c2[nt][1]);
            *(float2*)(o2b + (ms*16 + gr + 8) * 36 + col) = make_float2(c2[nt][2], c2[nt][3]);
        }
    }
    __syncthreads();

    // ---- P7: cross-jq reduce + add O2*rinv, store ----
    if (jq == 2) {
        for (int c = 0; c < 8; c++) *(float4*)(buf0 + i*36 + c*4) = *(float4*)(o + c*4);
    }
    if (jq == 3) {
        for (int c = 0; c < 8; c++) *(float4*)(buf1 + i*36 + c*4) = *(float4*)(o + c*4);
    }
    __syncthreads();
    if (jq == 0) {
        for (int c = 0; c < 32; c++) o[c] += buf0[i*36 + c];
    }
    if (jq == 1) {
        for (int c = 0; c < 32; c++) o[c] += buf1[i*36 + c];
    }
    __syncthreads();
    if (jq == 1) {
        for (int c = 0; c < 8; c++) *(float4*)(buf0 + i*36 + c*4) = *(float4*)(o + c*4);
    }
    __syncthreads();
    if (jq == 0) {
        float* dst = g_oh + ((size_t)b*LN + i)*CDIM + h*HD;
        #pragma unroll
        for (int c = 0; c < 8; c++) {
            float4 v;
            v.x = o[c*4+0] + buf0[i*36 + c*4+0] + o2b[i*36 + c*4+0] * rinv;
            v.y = o[c*4+1] + buf0[i*36 + c*4+1] + o2b[i*36 + c*4+1] * rinv;
            v.z = o[c*4+2] + buf0[i*36 + c*4+2] + o2b[i*36 + c*4+2] * rinv;
            v.w = o[c*4+3] + buf0[i*36 + c*4+3] + o2b[i*36 + c*4+3] * rinv;
            *(float4*)dst = v; dst += 4;
        }
    }
}

// =============================================================================
// K3 (warp-MMA tf32, 2 windows/block) — unchanged from passing R12.
// =============================================================================
__global__ __launch_bounds__(512) void proj_mma(const float* __restrict__ w,
                                                const float* __restrict__ bias,
                                                float* __restrict__ out) {
    extern __shared__ float sm[];
    float* xs = sm;                       // [2][128][132]
    float* ws = sm + 2*128*132;           // [128][132]
    float* bs = sm + 3*128*132;           // [128]
    const int t = threadIdx.x;
    const int wid = t >> 5, lane = t & 31;
    const int gr = lane >> 2, tc = lane & 3;
    const int w_i  = wid >> 3;
    const int wid8 = wid & 7;
    const int mrow = (wid8 & 3) * 32;
    const int n0b  = (wid8 >> 2) * 64;
    const int b = blockIdx.x * 2 + w_i;
    float* xw = xs + w_i * (128*132);

    stage128_512(xs,           g_oh + (size_t)(blockIdx.x*2)     * 16384, t);
    stage128_512(xs + 128*132, g_oh + (size_t)(blockIdx.x*2 + 1) * 16384, t);
    stage128_512(ws, w, t);
    if (t < 128) bs[t] = bias[t];
    __syncthreads();

    float c[8][8];
    #pragma unroll
    for (int nt = 0; nt < 8; nt++) {
        #pragma unroll
        for (int u = 0; u < 8; u++) c[nt][u] = 0.f;
    }

    #pragma unroll
    for (int ks = 0; ks < 16; ks++) {
        float a0[4], a1[4];
        a0[0] = xw[(mrow + gr)      * 132 + ks*8 + tc];
        a0[1] = xw[(mrow + gr + 8)  * 132 + ks*8 + tc];
        a0[2] = xw[(mrow + gr)      * 132 + ks*8 + tc + 4];
        a0[3] = xw[(mrow + gr + 8)  * 132 + ks*8 + tc + 4];
        a1[0] = xw[(mrow + gr + 16) * 132 + ks*8 + tc];
        a1[1] = xw[(mrow + gr + 24) * 132 + ks*8 + tc];
        a1[2] = xw[(mrow + gr + 16) * 132 + ks*8 + tc + 4];
        a1[3] = xw[(mrow + gr + 24) * 132 + ks*8 + tc + 4];
        #pragma unroll
        for (int nt = 0; nt < 8; nt++) {
            float b0 = ws[(n0b + nt*8 + gr) * 132 + ks*8 + tc];
            float b1 = ws[(n0b + nt*8 + gr) * 132 + ks*8 + tc + 4];
            mma8(c[nt],     a0, b0, b1);
            mma8(c[nt] + 4, a1, b0, b1);
        }
    }

    #pragma unroll
    for (int nt = 0; nt < 8; nt++) {
        int cch = n0b + nt*8 + 2*tc;
        float bb0 = bs[cch], bb1 = bs[cch + 1];
        float* base = out + ((size_t)b * LN) * CDIM + cch;
        #pragma unroll
        for (int mt = 0; mt < 2; mt++) {
            float* cr = c[nt] + mt*4;
            int r0 = mrow + mt * 16 + gr;
            *(float2*)(base +  r0      * CDIM) = make_float2(cr[0] + bb0, cr[1] + bb1);
            *(float2*)(base + (r0 + 8) * CDIM) = make_float2(cr[2] + bb0, cr[3] + bb1);
        }
    }
}

// =============================================================================
extern "C" void kernel_launch(void* const* d_in, const int* in_sizes, int n_in,
                              void* d_out, int out_size) {
    const float* x        = (const float*)d_in[0];
    const float* attn_msk = (const float*)d_in[1];
    const float* qkv_w    = (const float*)d_in[2];
    const float* qkv_b    = (const float*)d_in[3];
    const float* rpe      = (const float*)d_in[4];
    const float* proj_w   = (const float*)d_in[5];
    const float* proj_b   = (const float*)d_in[6];
    float* out = (float*)d_out;

    const int smem_k1   = (3*128*132 + 384) * sizeof(float);   // 204288
    const int smem_attn = 50500 * sizeof(float);               // 202000
    const int smem_k3   = (3*128*132 + 128) * sizeof(float);   // 203264

    cudaFuncSetAttribute(qkv_mma,     cudaFuncAttributeMaxDynamicSharedMemorySize, smem_k1);
    cudaFuncSetAttribute(attn_kernel, cudaFuncAttributeMaxDynamicSharedMemorySize, smem_attn);
    cudaFuncSetAttribute(proj_mma,    cudaFuncAttributeMaxDynamicSharedMemorySize, smem_k3);

    qkv_mma <<<B_TOT/2, 512, smem_k1>>>(x, qkv_w, qkv_b);
    attn_kernel<<<dim3(B_TOT, NH), 512, smem_attn>>>(attn_msk, rpe);
    proj_mma<<<B_TOT/2, 512, smem_k3>>>(proj_w, proj_b, out);
}

// round 14
// speedup vs baseline: 1.2720x; 1.1113x over previous
#include <cuda_runtime.h>
#include <cstdint>

#define B_TOT 2048
#define LN    128
#define CDIM  128
#define NH    4
#define HD    32
#define SCALEF 0.17677669529663687f   // 32^-0.5

typedef unsigned long long ull;

// ---------- f32x2 packed helpers ----------
__device__ __forceinline__ void fma2(ull& d, ull a, ull b) {
    asm("fma.rn.f32x2 %0, %1, %2, %0;" : "+l"(d) : "l"(a), "l"(b));
}
__device__ __forceinline__ float2 up2(ull u) {
    float2 f; asm("mov.b64 {%0, %1}, %2;" : "=f"(f.x), "=f"(f.y) : "l"(u)); return f;
}

// ---------- tf32 warp MMA ----------
__device__ __forceinline__ float tf32r(float f) {
    uint32_t u; asm("cvt.rna.tf32.f32 %0, %1;" : "=r"(u) : "f"(f));
    return __uint_as_float(u);
}
__device__ __forceinline__ void mma8(float* c, const float* a, float b0, float b1) {
    asm volatile(
        "mma.sync.aligned.m16n8k8.row.col.f32.tf32.tf32.f32 "
        "{%0,%1,%2,%3}, {%4,%5,%6,%7}, {%8,%9}, {%0,%1,%2,%3};"
        : "+f"(c[0]), "+f"(c[1]), "+f"(c[2]), "+f"(c[3])
        : "r"(__float_as_uint(a[0])), "r"(__float_as_uint(a[1])),
          "r"(__float_as_uint(a[2])), "r"(__float_as_uint(a[3])),
          "r"(__float_as_uint(b0)),  "r"(__float_as_uint(b1)));
}

// stage a 128x128 fp32 tile into smem stride-132 (tf32-rounded), 512 threads
__device__ __forceinline__ void stage128_512(float* dst, const float* __restrict__ src, int t) {
    const float4* g = (const float4*)src;
    #pragma unroll
    for (int r = 0; r < 8; r++) {
        int idx = r * 512 + t;
        float4 v = g[idx];
        int row = idx >> 5, col = (idx & 31) * 4;
        float* d = dst + row * 132 + col;
        d[0] = tf32r(v.x); d[1] = tf32r(v.y); d[2] = tf32r(v.z); d[3] = tf32r(v.w);
    }
}

// ------------------------- device scratch ---------------
__device__ float g_q [B_TOT*NH*LN*HD];
__device__ float g_k [B_TOT*NH*LN*HD];
__device__ float g_v [B_TOT*NH*LN*HD];
__device__ float g_oh[B_TOT*LN*CDIM];

// =============================================================================
// K1 (warp-MMA tf32, 2 windows/block) — unchanged from passing R12.
// =============================================================================
__global__ __launch_bounds__(512) void qkv_mma(const float* __restrict__ x,
                                               const float* __restrict__ w,
                                               const float* __restrict__ bias) {
    extern __shared__ float sm[];
    float* xs = sm;
    float* ws = sm + 2*128*132;
    float* bs = sm + 3*128*132;
    const int t = threadIdx.x;
    const int wid = t >> 5, lane = t & 31;
    const int gr = lane >> 2, tc = lane & 3;
    const int w_i  = wid >> 3;
    const int wid8 = wid & 7;
    const int mrow = (wid8 & 3) * 32;
    const int n0b  = (wid8 >> 2) * 64;
    const int b = blockIdx.x * 2 + w_i;
    float* xw = xs + w_i * (128*132);

    stage128_512(xs,           x + (size_t)(blockIdx.x*2)     * 16384, t);
    stage128_512(xs + 128*132, x + (size_t)(blockIdx.x*2 + 1) * 16384, t);
    if (t < 384) bs[t] = bias[t];

    for (int cc = 0; cc < 3; cc++) {
        __syncthreads();
        stage128_512(ws, w + cc * 16384, t);
        __syncthreads();

        float* arr = (cc == 0) ? g_q : ((cc == 1) ? g_k : g_v);
        const float scl = (cc == 0) ? SCALEF : 1.0f;

        float c[8][8];
        #pragma unroll
        for (int nt = 0; nt < 8; nt++) {
            #pragma unroll
            for (int u = 0; u < 8; u++) c[nt][u] = 0.f;
        }

        #pragma unroll
        for (int ks = 0; ks < 16; ks++) {
            float a0[4], a1[4];
            a0[0] = xw[(mrow + gr)      * 132 + ks*8 + tc];
            a0[1] = xw[(mrow + gr + 8)  * 132 + ks*8 + tc];
            a0[2] = xw[(mrow + gr)      * 132 + ks*8 + tc + 4];
            a0[3] = xw[(mrow + gr + 8)  * 132 + ks*8 + tc + 4];
            a1[0] = xw[(mrow + gr + 16) * 132 + ks*8 + tc];
            a1[1] = xw[(mrow + gr + 24) * 132 + ks*8 + tc];
            a1[2] = xw[(mrow + gr + 16) * 132 + ks*8 + tc + 4];
            a1[3] = xw[(mrow + gr + 24) * 132 + ks*8 + tc + 4];
            #pragma unroll
            for (int nt = 0; nt < 8; nt++) {
                float b0 = ws[(n0b + nt*8 + gr) * 132 + ks*8 + tc];
                float b1 = ws[(n0b + nt*8 + gr) * 132 + ks*8 + tc + 4];
                mma8(c[nt],     a0, b0, b1);
                mma8(c[nt] + 4, a1, b0, b1);
            }
        }

        #pragma unroll
        for (int nt = 0; nt < 8; nt++) {
            int cch = n0b + nt*8 + 2*tc;
            float bb0 = bs[cc*128 + cch], bb1 = bs[cc*128 + cch + 1];
            int h = cch >> 5, ch = cch & 31;
            float* base = arr + (((size_t)b * NH + h) * LN) * HD + ch;
            #pragma unroll
            for (int mt = 0; mt < 2; mt++) {
                float* cr = c[nt] + mt*4;
                int r0 = mrow + mt * 16 + gr;
                *(float2*)(base +  r0      * HD) = make_float2((cr[0]+bb0)*scl, (cr[1]+bb1)*scl);
                *(float2*)(base + (r0 + 8) * HD) = make_float2((cr[2]+bb0)*scl, (cr[3]+bb1)*scl);
            }
        }
    }
}

// =============================================================================
// K2 v4 (full tensor): QK, QR, P@V + W@tabv all via tf32 MMA; only kr scalar.
// smem (floats): q_s 4608 | k_s 4608 | tq 8100 | tab 8352 | scr[128][130] 16640
//                vt[32][132] 4224 | redm 512 | reds 512        = 47556 (190KB)
// W[128][122] (15616) overlays q_s+k_s+tq after QK GEMM.
// =============================================================================
__global__ __launch_bounds__(512, 1) void attn_kernel(const float* __restrict__ mask,
                                                      const float* __restrict__ rpe) {
    extern __shared__ float sm[];
    float* q_s  = sm;              // [128][36] tf32 (pre-scaled q)
    float* k_s  = sm + 4608;       // [128][36] tf32
    float* tq   = sm + 9216;       // [225][36] fp32: q_rpe * SCALEF
    float* tab  = sm + 17316;      // tabk [225][36] tf32 -> tabv^T [32][233] tf32
    float* scr  = sm + 25668;      // [128][130]: QR -> S -> P
    float* vt   = sm + 42308;      // [32][132] tf32 V^T
    float* redm = sm + 46532;      // [512]; later rinv[i] in [0,128)
    float* reds = sm + 47044;      // [512]
    float* W    = sm;              // [128][122] overlays q_s/k_s/tq

    const int b = blockIdx.x, h = blockIdx.y;
    const int t  = threadIdx.x;
    const int i  = t & 127;
    const int jq = t >> 7;
    const int wid = t >> 5, lane = t & 31;
    const int gr = lane >> 2, tc = lane & 3;
    const int ms = wid & 7;        // m-strip (16 rows)
    const int nh = wid >> 3;       // n-half

    // ---- P0: stage q,k (tf32), tq (fp32), tabk (tf32), V^T (tf32); att=mask
    {
        const float4* kg = (const float4*)(g_k + (((size_t)b*NH + h)*LN)*HD);
        const float4* qg = (const float4*)(g_q + (((size_t)b*NH + h)*LN)*HD);
        #pragma unroll
        for (int r = 0; r < 2; r++) {
            int idx4 = r*512 + t;
            float4 kv = kg[idx4], qv4 = qg[idx4];
            int row = idx4 >> 3, c4 = (idx4 & 7) * 4;
            float* dk = k_s + row*36 + c4;
            float* dq = q_s + row*36 + c4;
            dk[0] = tf32r(kv.x);  dk[1] = tf32r(kv.y);  dk[2] = tf32r(kv.z);  dk[3] = tf32r(kv.w);
            dq[0] = tf32r(qv4.x); dq[1] = tf32r(qv4.y); dq[2] = tf32r(qv4.z); dq[3] = tf32r(qv4.w);
        }
        const float* vbase = g_v + (((size_t)b*NH + h)*LN)*HD;
        #pragma unroll
        for (int r = 0; r < 8; r++) {
            int idx = r*512 + t;
            int j = idx >> 5, c = idx & 31;
            vt[c*132 + j] = tf32r(vbase[idx]);
        }
    }
    for (int idx = t; idx < 7200; idx += 512) {
        int tt = idx >> 5, u = idx & 31;
        tq[tt*36 + u]  = rpe[tt*384 + h*96 + u] * SCALEF;          // q_rpe*scale (kr)
        tab[tt*36 + u] = tf32r(rpe[tt*384 + h*96 + 32 + u]);       // k_rpe (QR)
    }
    float att[32];
    {
        const float4* mp = (const float4*)(mask + (size_t)(b & 127)*LN*LN + i*LN + jq*32);
        #pragma unroll
        for (int u = 0; u < 8; u++) {
            float4 m4 = mp[u];
            att[u*4+0] = m4.x; att[u*4+1] = m4.y; att[u*4+2] = m4.z; att[u*4+3] = m4.w;
        }
    }
    __syncthreads();                                               // (1)

    const int hi = i >> 4;
    const int wi = (i >> 1) & 7;

    // ---- P1: kr scalar (f32x2): att += k_j . (q_rpe[ridx]*scale)
    #pragma unroll
    for (int jj = 0; jj < 16; jj++) {
        int pj = jq*16 + jj;
        int ridx = (hi - (pj >> 3) + 7)*15 + (wi - (pj & 7) + 7);
        const ulonglong2* k0p = (const ulonglong2*)(k_s + pj*2*36);
        const ulonglong2* k1p = k0p + 9;
        const ulonglong2* tqp = (const ulonglong2*)(tq + ridx*36);
        ull kr0 = 0, kr1 = 0;
        #pragma unroll
        for (int u = 0; u < 8; u++) {
            ulonglong2 kv0 = k0p[u], kv1 = k1p[u], tqv = tqp[u];
            fma2(kr0, kv0.x, tqv.x); fma2(kr0, kv0.y, tqv.y);
            fma2(kr1, kv1.x, tqv.x); fma2(kr1, kv1.y, tqv.y);
        }
        float2 g0 = up2(kr0), g1 = up2(kr1);
        att[2*jj]   += g0.x + g0.y;
        att[2*jj+1] += g1.x + g1.y;
    }

    // ---- P2: QR GEMM (band width 120 per m-strip) -> scr stride 130
    {
        float fa[4][4];
        #pragma unroll
        for (int ks = 0; ks < 4; ks++) {
            fa[ks][0] = q_s[(ms*16 + gr)     * 36 + ks*8 + tc];
            fa[ks][1] = q_s[(ms*16 + gr + 8) * 36 + ks*8 + tc];
            fa[ks][2] = q_s[(ms*16 + gr)     * 36 + ks*8 + tc + 4];
            fa[ks][3] = q_s[(ms*16 + gr + 8) * 36 + ks*8 + tc + 4];
        }
        const int ntmax = nh ? 7 : 8;
        for (int nt = 0; nt < ntmax; nt++) {
            float c4[4] = {0.f, 0.f, 0.f, 0.f};
            #pragma unroll
            for (int ks = 0; ks < 4; ks++) {
                int trow = ms*15 + nh*64 + nt*8 + gr;
                float b0 = tab[trow*36 + ks*8 + tc];
                float b1 = tab[trow*36 + ks*8 + tc + 4];
                mma8(c4, fa[ks], b0, b1);
            }
            int col = nh*64 + nt*8 + 2*tc;
            *(float2*)(scr + (ms*16 + gr)     * 130 + col) = make_float2(c4[0], c4[1]);
            *(float2*)(scr + (ms*16 + gr + 8) * 130 + col) = make_float2(c4[2], c4[3]);
        }
    }
    __syncthreads();                                               // (2)

    // ---- P3: gather QR
    #pragma unroll
    for (int jj = 0; jj < 16; jj++) {
        int pj = jq*16 + jj;
        int lidx = (7 - (pj >> 3))*15 + (wi - (pj & 7) + 7);
        float qr = scr[i*130 + lidx];
        att[2*jj] += qr; att[2*jj+1] += qr;
    }
    __syncthreads();                                               // (3)

    // ---- P4: QK GEMM -> S (scr) stride 130
    {
        float fa[4][4];
        #pragma unroll
        for (int ks = 0; ks < 4; ks++) {
            fa[ks][0] = q_s[(ms*16 + gr)     * 36 + ks*8 + tc];
            fa[ks][1] = q_s[(ms*16 + gr + 8) * 36 + ks*8 + tc];
            fa[ks][2] = q_s[(ms*16 + gr)     * 36 + ks*8 + tc + 4];
            fa[ks][3] = q_s[(ms*16 + gr + 8) * 36 + ks*8 + tc + 4];
        }
        #pragma unroll
        for (int nt = 0; nt < 8; nt++) {
            float c4[4] = {0.f, 0.f, 0.f, 0.f};
            #pragma unroll
            for (int ks = 0; ks < 4; ks++) {
                int krow = nh*64 + nt*8 + gr;
                float b0 = k_s[krow*36 + ks*8 + tc];
                float b1 = k_s[krow*36 + ks*8 + tc + 4];
                mma8(c4, fa[ks], b0, b1);
            }
            int col = nh*64 + nt*8 + 2*tc;
            *(float2*)(scr + (ms*16 + gr)     * 130 + col) = make_float2(c4[0], c4[1]);
            *(float2*)(scr + (ms*16 + gr + 8) * 130 + col) = make_float2(c4[2], c4[3]);
        }
    }
    __syncthreads();                                               // (4)

    // ---- P5: att += S; softmax; P -> S (tf32); zero W; stage tabv^T
    #pragma unroll
    for (int u = 0; u < 32; u++) att[u] += scr[i*130 + jq*32 + u];

    float m = att[0];
    #pragma unroll
    for (int u = 1; u < 32; u++) m = fmaxf(m, att[u]);
    redm[jq*128 + i] = m;
    __syncthreads();                                               // (5)
    m = fmaxf(fmaxf(redm[i], redm[128 + i]), fmaxf(redm[256 + i], redm[384 + i]));
    float ls = 0.f;
    #pragma unroll
    for (int u = 0; u < 32; u++) { float e = __expf(att[u] - m); att[u] = e; ls += e; }
    reds[jq*128 + i] = ls;
    __syncthreads();                                               // (6)
    float rinv = 1.0f / (reds[i] + reds[128 + i] + reds[256 + i] + reds[384 + i]);
    if (jq == 0) redm[i] = rinv;

    {
        float4 z = make_float4(0.f, 0.f, 0.f, 0.f);
        float4* s4 = (float4*)W;
        #pragma unroll
        for (int r = 0; r < 8; r++) {
            int idx = r*512 + t;
            if (idx < 3904) s4[idx] = z;     // 128*122/4
        }
    }
    #pragma unroll
    for (int u = 0; u < 32; u++) scr[i*130 + jq*32 + u] = tf32r(att[u]);
    for (int idx = t; idx < 7200; idx += 512) {
        int tt = idx >> 5, u = idx & 31;
        tab[u*233 + tt] = tf32r(rpe[tt*384 + h*96 + 64 + u]);      // v_rpe^T
    }
    __syncthreads();                                               // (7)

    // scatter W (band-local)
    #pragma unroll
    for (int jj = 0; jj < 16; jj++) {
        int pj = jq*16 + jj;
        int lidx = (7 - (pj >> 3))*15 + (wi - (pj & 7) + 7);
        W[i*122 + lidx] = tf32r(att[2*jj] + att[2*jj+1]);
    }
    __syncthreads();                                               // (8)

    // ---- P6: fused O = P@V + W@tabv, x rinv, -> g_oh
    {
        float c2[2][4];
        #pragma unroll
        for (int nt = 0; nt < 2; nt++) {
            #pragma unroll
            for (int u = 0; u < 4; u++) c2[nt][u] = 0.f;
        }
        for (int ks = 0; ks < 16; ks++) {       // P@V, K=128
            float wa[4];
            wa[0] = scr[(ms*16 + gr)     * 130 + ks*8 + tc];
            wa[1] = scr[(ms*16 + gr + 8) * 130 + ks*8 + tc];
            wa[2] = scr[(ms*16 + gr)     * 130 + ks*8 + tc + 4];
            wa[3] = scr[(ms*16 + gr + 8) * 130 + ks*8 + tc + 4];
            #pragma unroll
            for (int nt = 0; nt < 2; nt++) {
                int vrow = nh*16 + nt*8 + gr;
                float b0 = vt[vrow*132 + ks*8 + tc];
                float b1 = vt[vrow*132 + ks*8 + tc + 4];
                mma8(c2[nt], wa, b0, b1);
            }
        }
        for (int ks = 0; ks < 15; ks++) {       // W@tabv, banded K=120
            float wa[4];
            wa[0] = W[(ms*16 + gr)     * 122 + ks*8 + tc];
            wa[1] = W[(ms*16 + gr + 8) * 122 + ks*8 + tc];
            wa[2] = W[(ms*16 + gr)     * 122 + ks*8 + tc + 4];
            wa[3] = W[(ms*16 + gr + 8) * 122 + ks*8 + tc + 4];
            #pragma unroll
            for (int nt = 0; nt < 2; nt++) {
                int crow = nh*16 + nt*8 + gr;
                float b0 = tab[crow*233 + ms*15 + ks*8 + tc];
                float b1 = tab[crow*233 + ms*15 + ks*8 + tc + 4];
                mma8(c2[nt], wa, b0, b1);
            }
        }
        int r0 = ms*16 + gr;
        float rinv0 = redm[r0], rinv1 = redm[r0 + 8];
        #pragma unroll
        for (int nt = 0; nt < 2; nt++) {
            int col = nh*16 + nt*8 + 2*tc;
            float* base = g_oh + ((size_t)b*LN)*CDIM + h*HD + col;
            *(float2*)(base +  r0      * CDIM) = make_float2(c2[nt][0]*rinv0, c2[nt][1]*rinv0);
            *(float2*)(base + (r0 + 8) * CDIM) = make_float2(c2[nt][2]*rinv1, c2[nt][3]*rinv1);
        }
    }
}

// =============================================================================
// K3 (warp-MMA tf32, 2 windows/block) — unchanged from passing R12.
// =============================================================================
__global__ __launch_bounds__(512) void proj_mma(const float* __restrict__ w,
                                                const float* __restrict__ bias,
                                                float* __restrict__ out) {
    extern __shared__ float sm[];
    float* xs = sm;
    float* ws = sm + 2*128*132;
    float* bs = sm + 3*128*132;
    const int t = threadIdx.x;
    const int wid = t >> 5, lane = t & 31;
    const int gr = lane >> 2, tc = lane & 3;
    const int w_i  = wid >> 3;
    const int wid8 = wid & 7;
    const int mrow = (wid8 & 3) * 32;
    const int n0b  = (wid8 >> 2) * 64;
    const int b = blockIdx.x * 2 + w_i;
    float* xw = xs + w_i * (128*132);

    stage128_512(xs,           g_oh + (size_t)(blockIdx.x*2)     * 16384, t);
    stage128_512(xs + 128*132, g_oh + (size_t)(blockIdx.x*2 + 1) * 16384, t);
    stage128_512(ws, w, t);
    if (t < 128) bs[t] = bias[t];
    __syncthreads();

    float c[8][8];
    #pragma unroll
    for (int nt = 0; nt < 8; nt++) {
        #pragma unroll
        for (int u = 0; u < 8; u++) c[nt][u] = 0.f;
    }

    #pragma unroll
    for (int ks = 0; ks < 16; ks++) {
        float a0[4], a1[4];
        a0[0] = xw[(mrow + gr)      * 132 + ks*8 + tc];
        a0[1] = xw[(mrow + gr + 8)  * 132 + ks*8 + tc];
        a0[2] = xw[(mrow + gr)      * 132 + ks*8 + tc + 4];
        a0[3] = xw[(mrow + gr + 8)  * 132 + ks*8 + tc + 4];
        a1[0] = xw[(mrow + gr + 16) * 132 + ks*8 + tc];
        a1[1] = xw[(mrow + gr + 24) * 132 + ks*8 + tc];
        a1[2] = xw[(mrow + gr + 16) * 132 + ks*8 + tc + 4];
        a1[3] = xw[(mrow + gr + 24) * 132 + ks*8 + tc + 4];
        #pragma unroll
        for (int nt = 0; nt < 8; nt++) {
            float b0 = ws[(n0b + nt*8 + gr) * 132 + ks*8 + tc];
            float b1 = ws[(n0b + nt*8 + gr) * 132 + ks*8 + tc + 4];
            mma8(c[nt],     a0, b0, b1);
            mma8(c[nt] + 4, a1, b0, b1);
        }
    }

    #pragma unroll
    for (int nt = 0; nt < 8; nt++) {
        int cch = n0b + nt*8 + 2*tc;
        float bb0 = bs[cch], bb1 = bs[cch + 1];
        float* base = out + ((size_t)b * LN) * CDIM + cch;
        #pragma unroll
        for (int mt = 0; mt < 2; mt++) {
            float* cr = c[nt] + mt*4;
            int r0 = mrow + mt * 16 + gr;
            *(float2*)(base +  r0      * CDIM) = make_float2(cr[0] + bb0, cr[1] + bb1);
            *(float2*)(base + (r0 + 8) * CDIM) = make_float2(cr[2] + bb0, cr[3] + bb1);
        }
    }
}

// =============================================================================
extern "C" void kernel_launch(void* const* d_in, const int* in_sizes, int n_in,
                              void* d_out, int out_size) {
    const float* x        = (const float*)d_in[0];
    const float* attn_msk = (const float*)d_in[1];
    const float* qkv_w    = (const float*)d_in[2];
    const float* qkv_b    = (const float*)d_in[3];
    const float* rpe      = (const float*)d_in[4];
    const float* proj_w   = (const float*)d_in[5];
    const float* proj_b   = (const float*)d_in[6];
    float* out = (float*)d_out;

    const int smem_k1   = (3*128*132 + 384) * sizeof(float);   // 204288
    const int smem_attn = 47556 * sizeof(float);               // 190224
    const int smem_k3   = (3*128*132 + 128) * sizeof(float);   // 203264

    cudaFuncSetAttribute(qkv_mma,     cudaFuncAttributeMaxDynamicSharedMemorySize, smem_k1);
    cudaFuncSetAttribute(attn_kernel, cudaFuncAttributeMaxDynamicSharedMemorySize, smem_attn);
    cudaFuncSetAttribute(proj_mma,    cudaFuncAttributeMaxDynamicSharedMemorySize, smem_k3);

    qkv_mma <<<B_TOT/2, 512, smem_k1>>>(x, qkv_w, qkv_b);
    attn_kernel<<<dim3(B_TOT, NH), 512, smem_attn>>>(attn_msk, rpe);
    proj_mma<<<B_TOT/2, 512, smem_k3>>>(proj_w, proj_b, out);
}

// round 15
// speedup vs baseline: 1.3390x; 1.0527x over previous
#include <cuda_runtime.h>
#include <cuda_bf16.h>
#include <cstdint>

#define B_TOT 2048
#define LN    128
#define CDIM  128
#define NH    4
#define HD    32
#define SCALEF 0.17677669529663687f   // 32^-0.5

typedef unsigned long long ull;

// ---------- tf32 warp MMA ----------
__device__ __forceinline__ float tf32r(float f) {
    uint32_t u; asm("cvt.rna.tf32.f32 %0, %1;" : "=r"(u) : "f"(f));
    return __uint_as_float(u);
}
__device__ __forceinline__ void mma8(float* c, const float* a, float b0, float b1) {
    asm volatile(
        "mma.sync.aligned.m16n8k8.row.col.f32.tf32.tf32.f32 "
        "{%0,%1,%2,%3}, {%4,%5,%6,%7}, {%8,%9}, {%0,%1,%2,%3};"
        : "+f"(c[0]), "+f"(c[1]), "+f"(c[2]), "+f"(c[3])
        : "r"(__float_as_uint(a[0])), "r"(__float_as_uint(a[1])),
          "r"(__float_as_uint(a[2])), "r"(__float_as_uint(a[3])),
          "r"(__float_as_uint(b0)),  "r"(__float_as_uint(b1)));
}
__device__ __forceinline__ uint32_t bf16pk(float lo, float hi) {
    uint32_t r;
    asm("cvt.rn.bf16x2.f32 %0, %1, %2;" : "=r"(r) : "f"(hi), "f"(lo));
    return r;
}

// stage a 128x128 fp32 tile into smem stride-132 (tf32-rounded), 512 threads
__device__ __forceinline__ void stage128_512(float* dst, const float* __restrict__ src, int t) {
    const float4* g = (const float4*)src;
    #pragma unroll
    for (int r = 0; r < 8; r++) {
        int idx = r * 512 + t;
        float4 v = g[idx];
        int row = idx >> 5, col = (idx & 31) * 4;
        float* d = dst + row * 132 + col;
        d[0] = tf32r(v.x); d[1] = tf32r(v.y); d[2] = tf32r(v.z); d[3] = tf32r(v.w);
    }
}

// ------------------------- device scratch ---------------
__device__ float g_q [B_TOT*NH*LN*HD];
__device__ float g_k [B_TOT*NH*LN*HD];
__device__ float g_v [B_TOT*NH*LN*HD];
__device__ float g_oh[B_TOT*LN*CDIM];

// =============================================================================
// K1 (warp-MMA tf32, 2 windows/block) — unchanged from passing R12.
// =============================================================================
__global__ __launch_bounds__(512) void qkv_mma(const float* __restrict__ x,
                                               const float* __restrict__ w,
                                               const float* __restrict__ bias) {
    extern __shared__ float sm[];
    float* xs = sm;
    float* ws = sm + 2*128*132;
    float* bs = sm + 3*128*132;
    const int t = threadIdx.x;
    const int wid = t >> 5, lane = t & 31;
    const int gr = lane >> 2, tc = lane & 3;
    const int w_i  = wid >> 3;
    const int wid8 = wid & 7;
    const int mrow = (wid8 & 3) * 32;
    const int n0b  = (wid8 >> 2) * 64;
    const int b = blockIdx.x * 2 + w_i;
    float* xw = xs + w_i * (128*132);

    stage128_512(xs,           x + (size_t)(blockIdx.x*2)     * 16384, t);
    stage128_512(xs + 128*132, x + (size_t)(blockIdx.x*2 + 1) * 16384, t);
    if (t < 384) bs[t] = bias[t];

    for (int cc = 0; cc < 3; cc++) {
        __syncthreads();
        stage128_512(ws, w + cc * 16384, t);
        __syncthreads();

        float* arr = (cc == 0) ? g_q : ((cc == 1) ? g_k : g_v);
        const float scl = (cc == 0) ? SCALEF : 1.0f;

        float c[8][8];
        #pragma unroll
        for (int nt = 0; nt < 8; nt++) {
            #pragma unroll
            for (int u = 0; u < 8; u++) c[nt][u] = 0.f;
        }

        #pragma unroll
        for (int ks = 0; ks < 16; ks++) {
            float a0[4], a1[4];
            a0[0] = xw[(mrow + gr)      * 132 + ks*8 + tc];
            a0[1] = xw[(mrow + gr + 8)  * 132 + ks*8 + tc];
            a0[2] = xw[(mrow + gr)      * 132 + ks*8 + tc + 4];
            a0[3] = xw[(mrow + gr + 8)  * 132 + ks*8 + tc + 4];
            a1[0] = xw[(mrow + gr + 16) * 132 + ks*8 + tc];
            a1[1] = xw[(mrow + gr + 24) * 132 + ks*8 + tc];
            a1[2] = xw[(mrow + gr + 16) * 132 + ks*8 + tc + 4];
            a1[3] = xw[(mrow + gr + 24) * 132 + ks*8 + tc + 4];
            #pragma unroll
            for (int nt = 0; nt < 8; nt++) {
                float b0 = ws[(n0b + nt*8 + gr) * 132 + ks*8 + tc];
                float b1 = ws[(n0b + nt*8 + gr) * 132 + ks*8 + tc + 4];
                mma8(c[nt],     a0, b0, b1);
                mma8(c[nt] + 4, a1, b0, b1);
            }
        }

        #pragma unroll
        for (int nt = 0; nt < 8; nt++) {
            int cch = n0b + nt*8 + 2*tc;
            float bb0 = bs[cc*128 + cch], bb1 = bs[cc*128 + cch + 1];
            int h = cch >> 5, ch = cch & 31;
            float* base = arr + (((size_t)b * NH + h) * LN) * HD + ch;
            #pragma unroll
            for (int mt = 0; mt < 2; mt++) {
                float* cr = c[nt] + mt*4;
                int r0 = mrow + mt * 16 + gr;
                *(float2*)(base +  r0      * HD) = make_float2((cr[0]+bb0)*scl, (cr[1]+bb1)*scl);
                *(float2*)(base + (r0 + 8) * HD) = make_float2((cr[2]+bb0)*scl, (cr[3]+bb1)*scl);
            }
        }
    }
}

// =============================================================================
// K2 v5: all four contractions on tensor pipe. QR banded; KR full-width into
// bf16 union buffer (scr recycles QR f32 -> KR bf16 -> S f32); fused O GEMM.
// smem floats: q_s 4608 | k_s 4608 | tabq[240][36] 8640 | tab 8352 |
//              scr 16640 | vt 4224 | redm 512 | reds 512 = 48096 (192.4KB)
// =============================================================================
__global__ __launch_bounds__(512, 1) void attn_kernel(const float* __restrict__ mask,
                                                      const float* __restrict__ rpe) {
    extern __shared__ float sm[];
    float* q_s  = sm;              // [128][36] tf32
    float* k_s  = sm + 4608;       // [128][36] tf32
    float* tabq = sm + 9216;       // [240][36] tf32: q_rpe*SCALEF, rows 225+ zero
    float* tab  = sm + 17856;      // tabk [225][36] tf32 -> tabv^T [32][233] tf32
    float* scr  = sm + 26208;      // union: QR f32 [128][130] / KR bf16 [128][242] / S f32 [128][130]
    float* vt   = sm + 42848;      // [32][132] tf32 V^T
    float* redm = sm + 47072;      // [512]; later rinv[i]
    float* reds = sm + 47584;      // [512]
    float* W    = sm;              // [128][122] overlays q_s/k_s/tabq after QK
    __nv_bfloat16* KRb = (__nv_bfloat16*)scr;

    const int b = blockIdx.x, h = blockIdx.y;
    const int t  = threadIdx.x;
    const int i  = t & 127;
    const int jq = t >> 7;
    const int wid = t >> 5, lane = t & 31;
    const int gr = lane >> 2, tc = lane & 3;
    const int ms = wid & 7;        // m-strip (16 rows)
    const int nh = wid >> 3;       // n-half

    // ---- P0: stage q,k (tf32), tabq (scaled tf32, padded), tabk, V^T; att=mask
    {
        const float4* kg = (const float4*)(g_k + (((size_t)b*NH + h)*LN)*HD);
        const float4* qg = (const float4*)(g_q + (((size_t)b*NH + h)*LN)*HD);
        #pragma unroll
        for (int r = 0; r < 2; r++) {
            int idx4 = r*512 + t;
            float4 kv = kg[idx4], qv4 = qg[idx4];
            int row = idx4 >> 3, c4 = (idx4 & 7) * 4;
            float* dk = k_s + row*36 + c4;
            float* dq = q_s + row*36 + c4;
            dk[0] = tf32r(kv.x);  dk[1] = tf32r(kv.y);  dk[2] = tf32r(kv.z);  dk[3] = tf32r(kv.w);
            dq[0] = tf32r(qv4.x); dq[1] = tf32r(qv4.y); dq[2] = tf32r(qv4.z); dq[3] = tf32r(qv4.w);
        }
        const float* vbase = g_v + (((size_t)b*NH + h)*LN)*HD;
        #pragma unroll
        for (int r = 0; r < 8; r++) {
            int idx = r*512 + t;
            int j = idx >> 5, c = idx & 31;
            vt[c*132 + j] = tf32r(vbase[idx]);
        }
    }
    for (int idx = t; idx < 7680; idx += 512) {        // tabq padded to 240 rows
        int r = idx >> 5, u = idx & 31;
        tabq[r*36 + u] = (r < 225) ? tf32r(rpe[r*384 + h*96 + u] * SCALEF) : 0.f;
    }
    for (int idx = t; idx < 7200; idx += 512) {        // tabk
        int r = idx >> 5, u = idx & 31;
        tab[r*36 + u] = tf32r(rpe[r*384 + h*96 + 32 + u]);
    }
    float att[32];
    {
        const float4* mp = (const float4*)(mask + (size_t)(b & 127)*LN*LN + i*LN + jq*32);
        #pragma unroll
        for (int u = 0; u < 8; u++) {
            float4 m4 = mp[u];
            att[u*4+0] = m4.x; att[u*4+1] = m4.y; att[u*4+2] = m4.z; att[u*4+3] = m4.w;
        }
    }
    __syncthreads();                                   // (1)

    const int hi = i >> 4;
    const int wi = (i >> 1) & 7;

    // ---- P1: QR GEMM (banded 120) -> scr f32 stride 130
    {
        float fa[4][4];
        #pragma unroll
        for (int ks = 0; ks < 4; ks++) {
            fa[ks][0] = q_s[(ms*16 + gr)     * 36 + ks*8 + tc];
            fa[ks][1] = q_s[(ms*16 + gr + 8) * 36 + ks*8 + tc];
            fa[ks][2] = q_s[(ms*16 + gr)     * 36 + ks*8 + tc + 4];
            fa[ks][3] = q_s[(ms*16 + gr + 8) * 36 + ks*8 + tc + 4];
        }
        const int ntmax = nh ? 7 : 8;
        for (int nt = 0; nt < ntmax; nt++) {
            float c4[4] = {0.f, 0.f, 0.f, 0.f};
            #pragma unroll
            for (int ks = 0; ks < 4; ks++) {
                int trow = ms*15 + nh*64 + nt*8 + gr;
                float b0 = tab[trow*36 + ks*8 + tc];
                float b1 = tab[trow*36 + ks*8 + tc + 4];
                mma8(c4, fa[ks], b0, b1);
            }
            int col = nh*64 + nt*8 + 2*tc;
            *(float2*)(scr + (ms*16 + gr)     * 130 + col) = make_float2(c4[0], c4[1]);
            *(float2*)(scr + (ms*16 + gr + 8) * 130 + col) = make_float2(c4[2], c4[3]);
        }
    }
    __syncthreads();                                   // (2)

    // ---- P2: gather QR (band-local)
    #pragma unroll
    for (int jj = 0; jj < 16; jj++) {
        int pj = jq*16 + jj;
        int lidx = (7 - (pj >> 3))*15 + (wi - (pj & 7) + 7);
        float qr = scr[i*130 + lidx];
        att[2*jj] += qr; att[2*jj+1] += qr;
    }
    __syncthreads();                                   // (3)

    // ---- P3: KR GEMM (full width 240) -> KRb bf16 stride 242
    {
        float fa[4][4];
        #pragma unroll
        for (int ks = 0; ks < 4; ks++) {
            fa[ks][0] = k_s[(ms*16 + gr)     * 36 + ks*8 + tc];
            fa[ks][1] = k_s[(ms*16 + gr + 8) * 36 + ks*8 + tc];
            fa[ks][2] = k_s[(ms*16 + gr)     * 36 + ks*8 + tc + 4];
            fa[ks][3] = k_s[(ms*16 + gr + 8) * 36 + ks*8 + tc + 4];
        }
        for (int nt = 0; nt < 15; nt++) {
            float c4[4] = {0.f, 0.f, 0.f, 0.f};
            #pragma unroll
            for (int ks = 0; ks < 4; ks++) {
                int trow = nh*120 + nt*8 + gr;
                float b0 = tabq[trow*36 + ks*8 + tc];
                float b1 = tabq[trow*36 + ks*8 + tc + 4];
                mma8(c4, fa[ks], b0, b1);
            }
            int col = nh*120 + nt*8 + 2*tc;
            int r0 = ms*16 + gr;
            *(uint32_t*)(KRb +  r0      * 242 + col) = bf16pk(c4[0], c4[1]);
            *(uint32_t*)(KRb + (r0 + 8) * 242 + col) = bf16pk(c4[2], c4[3]);
        }
    }
    __syncthreads();                                   // (4)

    // ---- P4: gather KR (2B loads)
    #pragma unroll
    for (int jj = 0; jj < 16; jj++) {
        int pj = jq*16 + jj;
        int ridx = (hi - (pj >> 3) + 7)*15 + (wi - (pj & 7) + 7);
        att[2*jj]   += __bfloat162float(KRb[(2*pj)    *242 + ridx]);
        att[2*jj+1] += __bfloat162float(KRb[(2*pj + 1)*242 + ridx]);
    }
    __syncthreads();                                   // (5)

    // ---- P5: QK GEMM -> S (scr f32 stride 130)
    {
        float fa[4][4];
        #pragma unroll
        for (int ks = 0; ks < 4; ks++) {
            fa[ks][0] = q_s[(ms*16 + gr)     * 36 + ks*8 + tc];
            fa[ks][1] = q_s[(ms*16 + gr + 8) * 36 + ks*8 + tc];
            fa[ks][2] = q_s[(ms*16 + gr)     * 36 + ks*8 + tc + 4];
            fa[ks][3] = q_s[(ms*16 + gr + 8) * 36 + ks*8 + tc + 4];
        }
        #pragma unroll
        for (int nt = 0; nt < 8; nt++) {
            float c4[4] = {0.f, 0.f, 0.f, 0.f};
            #pragma unroll
            for (int ks = 0; ks < 4; ks++) {
                int krow = nh*64 + nt*8 + gr;
                float b0 = k_s[krow*36 + ks*8 + tc];
                float b1 = k_s[krow*36 + ks*8 + tc + 4];
                mma8(c4, fa[ks], b0, b1);
            }
            int col = nh*64 + nt*8 + 2*tc;
            *(float2*)(scr + (ms*16 + gr)     * 130 + col) = make_float2(c4[0], c4[1]);
            *(float2*)(scr + (ms*16 + gr + 8) * 130 + col) = make_float2(c4[2], c4[3]);
        }
    }
    __syncthreads();                                   // (6)

    // ---- P6: att += S; softmax; P -> scr tf32; zero W; stage tabv^T
    #pragma unroll
    for (int u = 0; u < 32; u++) att[u] += scr[i*130 + jq*32 + u];

    float m = att[0];
    #pragma unroll
    for (int u = 1; u < 32; u++) m = fmaxf(m, att[u]);
    redm[jq*128 + i] = m;
    __syncthreads();                                   // (7)
    m = fmaxf(fmaxf(redm[i], redm[128 + i]), fmaxf(redm[256 + i], redm[384 + i]));
    float ls = 0.f;
    #pragma unroll
    for (int u = 0; u < 32; u++) { float e = __expf(att[u] - m); att[u] = e; ls += e; }
    reds[jq*128 + i] = ls;
    __syncthreads();                                   // (8)
    float rinv = 1.0f / (reds[i] + reds[128 + i] + reds[256 + i] + reds[384 + i]);
    if (jq == 0) redm[i] = rinv;

    {
        float4 z = make_float4(0.f, 0.f, 0.f, 0.f);
        float4* s4 = (float4*)W;
        #pragma unroll
        for (int r = 0; r < 8; r++) {
            int idx = r*512 + t;
            if (idx < 3904) s4[idx] = z;     // 128*122/4
        }
    }
    #pragma unroll
    for (int u = 0; u < 32; u++) scr[i*130 + jq*32 + u] = tf32r(att[u]);
    for (int idx = t; idx < 7200; idx += 512) {
        int tt = idx >> 5, u = idx & 31;
        tab[u*233 + tt] = tf32r(rpe[tt*384 + h*96 + 64 + u]);      // v_rpe^T
    }
    __syncthreads();                                   // (9)

    // scatter W (band-local)
    #pragma unroll
    for (int jj = 0; jj < 16; jj++) {
        int pj = jq*16 + jj;
        int lidx = (7 - (pj >> 3))*15 + (wi - (pj & 7) + 7);
        W[i*122 + lidx] = tf32r(att[2*jj] + att[2*jj+1]);
    }
    __syncthreads();                                   // (10)

    // ---- P7: fused O = P@V + W@tabv, x rinv, -> g_oh
    {
        float c2[2][4];
        #pragma unroll
        for (int nt = 0; nt < 2; nt++) {
            #pragma unroll
            for (int u = 0; u < 4; u++) c2[nt][u] = 0.f;
        }
        for (int ks = 0; ks < 16; ks++) {       // P@V, K=128
            float wa[4];
            wa[0] = scr[(ms*16 + gr)     * 130 + ks*8 + tc];
            wa[1] = scr[(ms*16 + gr + 8) * 130 + ks*8 + tc];
            wa[2] = scr[(ms*16 + gr)     * 130 + ks*8 + tc + 4];
            wa[3] = scr[(ms*16 + gr + 8) * 130 + ks*8 + tc + 4];
            #pragma unroll
            for (int nt = 0; nt < 2; nt++) {
                int vrow = nh*16 + nt*8 + gr;
                float b0 = vt[vrow*132 + ks*8 + tc];
                float b1 = vt[vrow*132 + ks*8 + tc + 4];
                mma8(c2[nt], wa, b0, b1);
            }
        }
        for (int ks = 0; ks < 15; ks++) {       // W@tabv, banded K=120
            float wa[4];
            wa[0] = W[(ms*16 + gr)     * 122 + ks*8 + tc];
            wa[1] = W[(ms*16 + gr + 8) * 122 + ks*8 + tc];
            wa[2] = W[(ms*16 + gr)     * 122 + ks*8 + tc + 4];
            wa[3] = W[(ms*16 + gr + 8) * 122 + ks*8 + tc + 4];
            #pragma unroll
            for (int nt = 0; nt < 2; nt++) {
                int crow = nh*16 + nt*8 + gr;
                float b0 = tab[crow*233 + ms*15 + ks*8 + tc];
                float b1 = tab[crow*233 + ms*15 + ks*8 + tc + 4];
                mma8(c2[nt], wa, b0, b1);
            }
        }
        int r0 = ms*16 + gr;
        float rinv0 = redm[r0], rinv1 = redm[r0 + 8];
        #pragma unroll
        for (int nt = 0; nt < 2; nt++) {
            int col = nh*16 + nt*8 + 2*tc;
            float* base = g_oh + ((size_t)b*LN)*CDIM + h*HD + col;
            *(float2*)(base +  r0      * CDIM) = make_float2(c2[nt][0]*rinv0, c2[nt][1]*rinv0);
            *(float2*)(base + (r0 + 8) * CDIM) = make_float2(c2[nt][2]*rinv1, c2[nt][3]*rinv1);
        }
    }
}

// =============================================================================
// K3 (warp-MMA tf32, 2 windows/block) — unchanged from passing R12.
// =============================================================================
__global__ __launch_bounds__(512) void proj_mma(const float* __restrict__ w,
                                                const float* __restrict__ bias,
                                                float* __restrict__ out) {
    extern __shared__ float sm[];
    float* xs = sm;
    float* ws = sm + 2*128*132;
    float* bs = sm + 3*128*132;
    const int t = threadIdx.x;
    const int wid = t >> 5, lane = t & 31;
    const int gr = lane >> 2, tc = lane & 3;
    const int w_i  = wid >> 3;
    const int wid8 = wid & 7;
    const int mrow = (wid8 & 3) * 32;
    const int n0b  = (wid8 >> 2) * 64;
    const int b = blockIdx.x * 2 + w_i;
    float* xw = xs + w_i * (128*132);

    stage128_512(xs,           g_oh + (size_t)(blockIdx.x*2)     * 16384, t);
    stage128_512(xs + 128*132, g_oh + (size_t)(blockIdx.x*2 + 1) * 16384, t);
    stage128_512(ws, w, t);
    if (t < 128) bs[t] = bias[t];
    __syncthreads();

    float c[8][8];
    #pragma unroll
    for (int nt = 0; nt < 8; nt++) {
        #pragma unroll
        for (int u = 0; u < 8; u++) c[nt][u] = 0.f;
    }

    #pragma unroll
    for (int ks = 0; ks < 16; ks++) {
        float a0[4], a1[4];
        a0[0] = xw[(mrow + gr)      * 132 + ks*8 + tc];
        a0[1] = xw[(mrow + gr + 8)  * 132 + ks*8 + tc];
        a0[2] = xw[(mrow + gr)      * 132 + ks*8 + tc + 4];
        a0[3] = xw[(mrow + gr + 8)  * 132 + ks*8 + tc + 4];
        a1[0] = xw[(mrow + gr + 16) * 132 + ks*8 + tc];
        a1[1] = xw[(mrow + gr + 24) * 132 + ks*8 + tc];
        a1[2] = xw[(mrow + gr + 16) * 132 + ks*8 + tc + 4];
        a1[3] = xw[(mrow + gr + 24) * 132 + ks*8 + tc + 4];
        #pragma unroll
        for (int nt = 0; nt < 8; nt++) {
            float b0 = ws[(n0b + nt*8 + gr) * 132 + ks*8 + tc];
            float b1 = ws[(n0b + nt*8 + gr) * 132 + ks*8 + tc + 4];
            mma8(c[nt],     a0, b0, b1);
            mma8(c[nt] + 4, a1, b0, b1);
        }
    }

    #pragma unroll
    for (int nt = 0; nt < 8; nt++) {
        int cch = n0b + nt*8 + 2*tc;
        float bb0 = bs[cch], bb1 = bs[cch + 1];
        float* base = out + ((size_t)b * LN) * CDIM + cch;
        #pragma unroll
        for (int mt = 0; mt < 2; mt++) {
            float* cr = c[nt] + mt*4;
            int r0 = mrow + mt * 16 + gr;
            *(float2*)(base +  r0      * CDIM) = make_float2(cr[0] + bb0, cr[1] + bb1);
            *(float2*)(base + (r0 + 8) * CDIM) = make_float2(cr[2] + bb0, cr[3] + bb1);
        }
    }
}

// =============================================================================
extern "C" void kernel_launch(void* const* d_in, const int* in_sizes, int n_in,
                              void* d_out, int out_size) {
    const float* x        = (const float*)d_in[0];
    const float* attn_msk = (const float*)d_in[1];
    const float* qkv_w    = (const float*)d_in[2];
    const float* qkv_b    = (const float*)d_in[3];
    const float* rpe      = (const float*)d_in[4];
    const float* proj_w   = (const float*)d_in[5];
    const float* proj_b   = (const float*)d_in[6];
    float* out = (float*)d_out;

    const int smem_k1   = (3*128*132 + 384) * sizeof(float);   // 204288
    const int smem_attn = 48096 * sizeof(float);               // 192384
    const int smem_k3   = (3*128*132 + 128) * sizeof(float);   // 203264

    cudaFuncSetAttribute(qkv_mma,     cudaFuncAttributeMaxDynamicSharedMemorySize, smem_k1);
    cudaFuncSetAttribute(attn_kernel, cudaFuncAttributeMaxDynamicSharedMemorySize, smem_attn);
    cudaFuncSetAttribute(proj_mma,    cudaFuncAttributeMaxDynamicSharedMemorySize, smem_k3);

    qkv_mma <<<B_TOT/2, 512, smem_k1>>>(x, qkv_w, qkv_b);
    attn_kernel<<<dim3(B_TOT, NH), 512, smem_attn>>>(attn_msk, rpe);
    proj_mma<<<B_TOT/2, 512, smem_k3>>>(proj_w, proj_b, out);
}

// round 16
// speedup vs baseline: 1.4409x; 1.0761x over previous
#include <cuda_runtime.h>
#include <cuda_bf16.h>
#include <cstdint>

#define B_TOT 2048
#define LN    128
#define CDIM  128
#define NH    4
#define HD    32
#define SCALEF 0.17677669529663687f   // 32^-0.5

typedef unsigned long long ull;

// ---------- tf32 warp MMA ----------
__device__ __forceinline__ float tf32r(float f) {
    uint32_t u; asm("cvt.rna.tf32.f32 %0, %1;" : "=r"(u) : "f"(f));
    return __uint_as_float(u);
}
__device__ __forceinline__ void mma8(float* c, const float* a, float b0, float b1) {
    asm volatile(
        "mma.sync.aligned.m16n8k8.row.col.f32.tf32.tf32.f32 "
        "{%0,%1,%2,%3}, {%4,%5,%6,%7}, {%8,%9}, {%0,%1,%2,%3};"
        : "+f"(c[0]), "+f"(c[1]), "+f"(c[2]), "+f"(c[3])
        : "r"(__float_as_uint(a[0])), "r"(__float_as_uint(a[1])),
          "r"(__float_as_uint(a[2])), "r"(__float_as_uint(a[3])),
          "r"(__float_as_uint(b0)),  "r"(__float_as_uint(b1)));
}
__device__ __forceinline__ uint32_t bf16pk(float lo, float hi) {
    uint32_t r;
    asm("cvt.rn.bf16x2.f32 %0, %1, %2;" : "=r"(r) : "f"(hi), "f"(lo));
    return r;
}

// stage a 128x128 fp32 tile into smem stride-132 (tf32-rounded), 512 threads
__device__ __forceinline__ void stage128_512(float* dst, const float* __restrict__ src, int t) {
    const float4* g = (const float4*)src;
    #pragma unroll
    for (int r = 0; r < 8; r++) {
        int idx = r * 512 + t;
        float4 v = g[idx];
        int row = idx >> 5, col = (idx & 31) * 4;
        float* d = dst + row * 132 + col;
        d[0] = tf32r(v.x); d[1] = tf32r(v.y); d[2] = tf32r(v.z); d[3] = tf32r(v.w);
    }
}

// ------------------------- device scratch ---------------
__device__ float g_q [B_TOT*NH*LN*HD];
__device__ float g_k [B_TOT*NH*LN*HD];
__device__ float g_v [B_TOT*NH*LN*HD];
__device__ float g_oh[B_TOT*LN*CDIM];

// =============================================================================
// K1 (warp-MMA tf32, 2 windows/block) — unchanged from passing R12.
// =============================================================================
__global__ __launch_bounds__(512) void qkv_mma(const float* __restrict__ x,
                                               const float* __restrict__ w,
                                               const float* __restrict__ bias) {
    extern __shared__ float sm[];
    float* xs = sm;
    float* ws = sm + 2*128*132;
    float* bs = sm + 3*128*132;
    const int t = threadIdx.x;
    const int wid = t >> 5, lane = t & 31;
    const int gr = lane >> 2, tc = lane & 3;
    const int w_i  = wid >> 3;
    const int wid8 = wid & 7;
    const int mrow = (wid8 & 3) * 32;
    const int n0b  = (wid8 >> 2) * 64;
    const int b = blockIdx.x * 2 + w_i;
    float* xw = xs + w_i * (128*132);

    stage128_512(xs,           x + (size_t)(blockIdx.x*2)     * 16384, t);
    stage128_512(xs + 128*132, x + (size_t)(blockIdx.x*2 + 1) * 16384, t);
    if (t < 384) bs[t] = bias[t];

    for (int cc = 0; cc < 3; cc++) {
        __syncthreads();
        stage128_512(ws, w + cc * 16384, t);
        __syncthreads();

        float* arr = (cc == 0) ? g_q : ((cc == 1) ? g_k : g_v);
        const float scl = (cc == 0) ? SCALEF : 1.0f;

        float c[8][8];
        #pragma unroll
        for (int nt = 0; nt < 8; nt++) {
            #pragma unroll
            for (int u = 0; u < 8; u++) c[nt][u] = 0.f;
        }

        #pragma unroll
        for (int ks = 0; ks < 16; ks++) {
            float a0[4], a1[4];
            a0[0] = xw[(mrow + gr)      * 132 + ks*8 + tc];
            a0[1] = xw[(mrow + gr + 8)  * 132 + ks*8 + tc];
            a0[2] = xw[(mrow + gr)      * 132 + ks*8 + tc + 4];
            a0[3] = xw[(mrow + gr + 8)  * 132 + ks*8 + tc + 4];
            a1[0] = xw[(mrow + gr + 16) * 132 + ks*8 + tc];
            a1[1] = xw[(mrow + gr + 24) * 132 + ks*8 + tc];
            a1[2] = xw[(mrow + gr + 16) * 132 + ks*8 + tc + 4];
            a1[3] = xw[(mrow + gr + 24) * 132 + ks*8 + tc + 4];
            #pragma unroll
            for (int nt = 0; nt < 8; nt++) {
                float b0 = ws[(n0b + nt*8 + gr) * 132 + ks*8 + tc];
                float b1 = ws[(n0b + nt*8 + gr) * 132 + ks*8 + tc + 4];
                mma8(c[nt],     a0, b0, b1);
                mma8(c[nt] + 4, a1, b0, b1);
            }
        }

        #pragma unroll
        for (int nt = 0; nt < 8; nt++) {
            int cch = n0b + nt*8 + 2*tc;
            float bb0 = bs[cc*128 + cch], bb1 = bs[cc*128 + cch + 1];
            int h = cch >> 5, ch = cch & 31;
            float* base = arr + (((size_t)b * NH + h) * LN) * HD + ch;
            #pragma unroll
            for (int mt = 0; mt < 2; mt++) {
                float* cr = c[nt] + mt*4;
                int r0 = mrow + mt * 16 + gr;
                *(float2*)(base +  r0      * HD) = make_float2((cr[0]+bb0)*scl, (cr[1]+bb1)*scl);
                *(float2*)(base + (r0 + 8) * HD) = make_float2((cr[2]+bb0)*scl, (cr[3]+bb1)*scl);
            }
        }
    }
}

// =============================================================================
// K2 v6: same math as R15 (all-tensor), widened to 1024 threads / 32 warps.
// warp = (m-strip ms 0-7) x (n-quarter nq 0-3); thread owns 16 j's (jq 0-7).
// smem floats: q_s 4608 | k_s 4608 | tabq 8640 | tab 8352 | scr 16640 |
//              vt 4224 | redm 1024 | reds 1024 = 49120 (196.5KB)
// =============================================================================
__global__ __launch_bounds__(1024, 1) void attn_kernel(const float* __restrict__ mask,
                                                       const float* __restrict__ rpe) {
    extern __shared__ float sm[];
    float* q_s  = sm;              // [128][36] tf32
    float* k_s  = sm + 4608;       // [128][36] tf32
    float* tabq = sm + 9216;       // [240][36] tf32: q_rpe*SCALEF, rows 225+ zero
    float* tab  = sm + 17856;      // tabk [225][36] tf32 -> tabv^T [32][233] tf32
    float* scr  = sm + 26208;      // union: QR f32 [128][130] / KR bf16 [128][242] / S f32 [128][130]
    float* vt   = sm + 42848;      // [32][132] tf32 V^T
    float* redm = sm + 47072;      // [1024]; later rinv[i]
    float* reds = sm + 48096;      // [1024]
    float* W    = sm;              // [128][122] overlays q_s/k_s/tabq after QK
    __nv_bfloat16* KRb = (__nv_bfloat16*)scr;

    const int b = blockIdx.x, h = blockIdx.y;
    const int t  = threadIdx.x;
    const int i  = t & 127;
    const int jq = t >> 7;         // 0..7, owns j in [jq*16, jq*16+16)
    const int wid = t >> 5, lane = t & 31;
    const int gr = lane >> 2, tc = lane & 3;
    const int ms = wid & 7;        // m-strip (16 rows)
    const int nq = wid >> 3;       // n-quarter (0..3)

    // ---- P0: stage q,k (tf32), tabq (scaled tf32, padded), tabk, V^T; att=mask
    {
        const float4* kg = (const float4*)(g_k + (((size_t)b*NH + h)*LN)*HD);
        const float4* qg = (const float4*)(g_q + (((size_t)b*NH + h)*LN)*HD);
        int idx4 = t;              // 1024 float4 total
        float4 kv = kg[idx4], qv4 = qg[idx4];
        int row = idx4 >> 3, c4 = (idx4 & 7) * 4;
        float* dk = k_s + row*36 + c4;
        float* dq = q_s + row*36 + c4;
        dk[0] = tf32r(kv.x);  dk[1] = tf32r(kv.y);  dk[2] = tf32r(kv.z);  dk[3] = tf32r(kv.w);
        dq[0] = tf32r(qv4.x); dq[1] = tf32r(qv4.y); dq[2] = tf32r(qv4.z); dq[3] = tf32r(qv4.w);

        const float* vbase = g_v + (((size_t)b*NH + h)*LN)*HD;
        #pragma unroll
        for (int r = 0; r < 4; r++) {
            int idx = r*1024 + t;
            int j = idx >> 5, c = idx & 31;
            vt[c*132 + j] = tf32r(vbase[idx]);
        }
    }
    for (int idx = t; idx < 7680; idx += 1024) {       // tabq padded to 240 rows
        int r = idx >> 5, u = idx & 31;
        tabq[r*36 + u] = (r < 225) ? tf32r(rpe[r*384 + h*96 + u] * SCALEF) : 0.f;
    }
    for (int idx = t; idx < 7200; idx += 1024) {       // tabk
        int r = idx >> 5, u = idx & 31;
        tab[r*36 + u] = tf32r(rpe[r*384 + h*96 + 32 + u]);
    }
    float att[16];
    {
        const float4* mp = (const float4*)(mask + (size_t)(b & 127)*LN*LN + i*LN + jq*16);
        #pragma unroll
        for (int u = 0; u < 4; u++) {
            float4 m4 = mp[u];
            att[u*4+0] = m4.x; att[u*4+1] = m4.y; att[u*4+2] = m4.z; att[u*4+3] = m4.w;
        }
    }
    __syncthreads();                                   // (1)

    const int hi = i >> 4;
    const int wi = (i >> 1) & 7;

    // ---- P1: QR GEMM (banded 120, 15 nt-tiles over 4 nq) -> scr f32 stride 130
    {
        float fa[4][4];
        #pragma unroll
        for (int ks = 0; ks < 4; ks++) {
            fa[ks][0] = q_s[(ms*16 + gr)     * 36 + ks*8 + tc];
            fa[ks][1] = q_s[(ms*16 + gr + 8) * 36 + ks*8 + tc];
            fa[ks][2] = q_s[(ms*16 + gr)     * 36 + ks*8 + tc + 4];
            fa[ks][3] = q_s[(ms*16 + gr + 8) * 36 + ks*8 + tc + 4];
        }
        int nt_end = nq*4 + 4; if (nt_end > 15) nt_end = 15;
        for (int nt = nq*4; nt < nt_end; nt++) {
            float c4[4] = {0.f, 0.f, 0.f, 0.f};
            #pragma unroll
            for (int ks = 0; ks < 4; ks++) {
                int trow = ms*15 + nt*8 + gr;
                float b0 = tab[trow*36 + ks*8 + tc];
                float b1 = tab[trow*36 + ks*8 + tc + 4];
                mma8(c4, fa[ks], b0, b1);
            }
            int col = nt*8 + 2*tc;
            *(float2*)(scr + (ms*16 + gr)     * 130 + col) = make_float2(c4[0], c4[1]);
            *(float2*)(scr + (ms*16 + gr + 8) * 130 + col) = make_float2(c4[2], c4[3]);
        }
    }
    __syncthreads();                                   // (2)

    // ---- P2: gather QR (band-local, 8 pairs per thread)
    #pragma unroll
    for (int jj = 0; jj < 8; jj++) {
        int pj = jq*8 + jj;
        int lidx = (7 - (pj >> 3))*15 + (wi - (pj & 7) + 7);
        float qr = scr[i*130 + lidx];
        att[2*jj] += qr; att[2*jj+1] += qr;
    }
    __syncthreads();                                   // (3)

    // ---- P3: KR GEMM (full width 240, 30 nt-tiles strided over nq) -> KRb bf16
    {
        float fa[4][4];
        #pragma unroll
        for (int ks = 0; ks < 4; ks++) {
            fa[ks][0] = k_s[(ms*16 + gr)     * 36 + ks*8 + tc];
            fa[ks][1] = k_s[(ms*16 + gr + 8) * 36 + ks*8 + tc];
            fa[ks][2] = k_s[(ms*16 + gr)     * 36 + ks*8 + tc + 4];
            fa[ks][3] = k_s[(ms*16 + gr + 8) * 36 + ks*8 + tc + 4];
        }
        for (int nt = nq; nt < 30; nt += 4) {
            float c4[4] = {0.f, 0.f, 0.f, 0.f};
            #pragma unroll
            for (int ks = 0; ks < 4; ks++) {
                int trow = nt*8 + gr;
                float b0 = tabq[trow*36 + ks*8 + tc];
                float b1 = tabq[trow*36 + ks*8 + tc + 4];
                mma8(c4, fa[ks], b0, b1);
            }
            int col = nt*8 + 2*tc;
            int r0 = ms*16 + gr;
            *(uint32_t*)(KRb +  r0      * 242 + col) = bf16pk(c4[0], c4[1]);
            *(uint32_t*)(KRb + (r0 + 8) * 242 + col) = bf16pk(c4[2], c4[3]);
        }
    }
    __syncthreads();                                   // (4)

    // ---- P4: gather KR (2B loads)
    #pragma unroll
    for (int jj = 0; jj < 8; jj++) {
        int pj = jq*8 + jj;
        int ridx = (hi - (pj >> 3) + 7)*15 + (wi - (pj & 7) + 7);
        att[2*jj]   += __bfloat162float(KRb[(2*pj)    *242 + ridx]);
        att[2*jj+1] += __bfloat162float(KRb[(2*pj + 1)*242 + ridx]);
    }
    __syncthreads();                                   // (5)

    // ---- P5: QK GEMM (16 nt-tiles over 4 nq) -> S (scr f32 stride 130)
    {
        float fa[4][4];
        #pragma unroll
        for (int ks = 0; ks < 4; ks++) {
            fa[ks][0] = q_s[(ms*16 + gr)     * 36 + ks*8 + tc];
            fa[ks][1] = q_s[(ms*16 + gr + 8) * 36 + ks*8 + tc];
            fa[ks][2] = q_s[(ms*16 + gr)     * 36 + ks*8 + tc + 4];
            fa[ks][3] = q_s[(ms*16 + gr + 8) * 36 + ks*8 + tc + 4];
        }
        #pragma unroll
        for (int nn = 0; nn < 4; nn++) {
            int nt = nq*4 + nn;
            float c4[4] = {0.f, 0.f, 0.f, 0.f};
            #pragma unroll
            for (int ks = 0; ks < 4; ks++) {
                int krow = nt*8 + gr;
                float b0 = k_s[krow*36 + ks*8 + tc];
                float b1 = k_s[krow*36 + ks*8 + tc + 4];
                mma8(c4, fa[ks], b0, b1);
            }
            int col = nt*8 + 2*tc;
            *(float2*)(scr + (ms*16 + gr)     * 130 + col) = make_float2(c4[0], c4[1]);
            *(float2*)(scr + (ms*16 + gr + 8) * 130 + col) = make_float2(c4[2], c4[3]);
        }
    }
    __syncthreads();                                   // (6)

    // ---- P6: att += S; softmax over 8 partials; P -> scr tf32; zero W; tabv^T
    #pragma unroll
    for (int u = 0; u < 16; u++) att[u] += scr[i*130 + jq*16 + u];

    float m = att[0];
    #pragma unroll
    for (int u = 1; u < 16; u++) m = fmaxf(m, att[u]);
    redm[jq*128 + i] = m;
    __syncthreads();                                   // (7)
    #pragma unroll
    for (int p = 0; p < 8; p++) m = fmaxf(m, redm[p*128 + i]);
    float ls = 0.f;
    #pragma unroll
    for (int u = 0; u < 16; u++) { float e = __expf(att[u] - m); att[u] = e; ls += e; }
    reds[jq*128 + i] = ls;
    __syncthreads();                                   // (8)
    float lsum = 0.f;
    #pragma unroll
    for (int p = 0; p < 8; p++) lsum += reds[p*128 + i];
    float rinv = 1.0f / lsum;
    if (jq == 0) redm[i] = rinv;

    {
        float4 z = make_float4(0.f, 0.f, 0.f, 0.f);
        float4* s4 = (float4*)W;
        #pragma unroll
        for (int r = 0; r < 4; r++) {
            int idx = r*1024 + t;
            if (idx < 3904) s4[idx] = z;     // 128*122/4
        }
    }
    #pragma unroll
    for (int u = 0; u < 16; u++) scr[i*130 + jq*16 + u] = tf32r(att[u]);
    for (int idx = t; idx < 7200; idx += 1024) {
        int tt = idx >> 5, u = idx & 31;
        tab[u*233 + tt] = tf32r(rpe[tt*384 + h*96 + 64 + u]);      // v_rpe^T
    }
    __syncthreads();                                   // (9)

    // scatter W (band-local)
    #pragma unroll
    for (int jj = 0; jj < 8; jj++) {
        int pj = jq*8 + jj;
        int lidx = (7 - (pj >> 3))*15 + (wi - (pj & 7) + 7);
        W[i*122 + lidx] = tf32r(att[2*jj] + att[2*jj+1]);
    }
    __syncthreads();                                   // (10)

    // ---- P7: fused O = P@V + W@tabv (1 nt per warp), x rinv, -> g_oh
    {
        float c4[4] = {0.f, 0.f, 0.f, 0.f};
        for (int ks = 0; ks < 16; ks++) {       // P@V, K=128
            float wa[4];
            wa[0] = scr[(ms*16 + gr)     * 130 + ks*8 + tc];
            wa[1] = scr[(ms*16 + gr + 8) * 130 + ks*8 + tc];
            wa[2] = scr[(ms*16 + gr)     * 130 + ks*8 + tc + 4];
            wa[3] = scr[(ms*16 + gr + 8) * 130 + ks*8 + tc + 4];
            int vrow = nq*8 + gr;
            float b0 = vt[vrow*132 + ks*8 + tc];
            float b1 = vt[vrow*132 + ks*8 + tc + 4];
            mma8(c4, wa, b0, b1);
        }
        for (int ks = 0; ks < 15; ks++) {       // W@tabv, banded K=120
            float wa[4];
            wa[0] = W[(ms*16 + gr)     * 122 + ks*8 + tc];
            wa[1] = W[(ms*16 + gr + 8) * 122 + ks*8 + tc];
            wa[2] = W[(ms*16 + gr)     * 122 + ks*8 + tc + 4];
            wa[3] = W[(ms*16 + gr + 8) * 122 + ks*8 + tc + 4];
            int crow = nq*8 + gr;
            float b0 = tab[crow*233 + ms*15 + ks*8 + tc];
            float b1 = tab[crow*233 + ms*15 + ks*8 + tc + 4];
            mma8(c4, wa, b0, b1);
        }
        int r0 = ms*16 + gr;
        float rinv0 = redm[r0], rinv1 = redm[r0 + 8];
        int col = nq*8 + 2*tc;
        float* base = g_oh + ((size_t)b*LN)*CDIM + h*HD + col;
        *(float2*)(base +  r0      * CDIM) = make_float2(c4[0]*rinv0, c4[1]*rinv0);
        *(float2*)(base + (r0 + 8) * CDIM) = make_float2(c4[2]*rinv1, c4[3]*rinv1);
    }
}

// =============================================================================
// K3 (warp-MMA tf32, 2 windows/block) — unchanged from passing R12.
// =============================================================================
__global__ __launch_bounds__(512) void proj_mma(const float* __restrict__ w,
                                                const float* __restrict__ bias,
                                                float* __restrict__ out) {
    extern __shared__ float sm[];
    float* xs = sm;
    float* ws = sm + 2*128*132;
    float* bs = sm + 3*128*132;
    const int t = threadIdx.x;
    const int wid = t >> 5, lane = t & 31;
    const int gr = lane >> 2, tc = lane & 3;
    const int w_i  = wid >> 3;
    const int wid8 = wid & 7;
    const int mrow = (wid8 & 3) * 32;
    const int n0b  = (wid8 >> 2) * 64;
    const int b = blockIdx.x * 2 + w_i;
    float* xw = xs + w_i * (128*132);

    stage128_512(xs,           g_oh + (size_t)(blockIdx.x*2)     * 16384, t);
    stage128_512(xs + 128*132, g_oh + (size_t)(blockIdx.x*2 + 1) * 16384, t);
    stage128_512(ws, w, t);
    if (t < 128) bs[t] = bias[t];
    __syncthreads();

    float c[8][8];
    #pragma unroll
    for (int nt = 0; nt < 8; nt++) {
        #pragma unroll
        for (int u = 0; u < 8; u++) c[nt][u] = 0.f;
    }

    #pragma unroll
    for (int ks = 0; ks < 16; ks++) {
        float a0[4], a1[4];
        a0[0] = xw[(mrow + gr)      * 132 + ks*8 + tc];
        a0[1] = xw[(mrow + gr + 8)  * 132 + ks*8 + tc];
        a0[2] = xw[(mrow + gr)      * 132 + ks*8 + tc + 4];
        a0[3] = xw[(mrow + gr + 8)  * 132 + ks*8 + tc + 4];
        a1[0] = xw[(mrow + gr + 16) * 132 + ks*8 + tc];
        a1[1] = xw[(mrow + gr + 24) * 132 + ks*8 + tc];
        a1[2] = xw[(mrow + gr + 16) * 132 + ks*8 + tc + 4];
        a1[3] = xw[(mrow + gr + 24) * 132 + ks*8 + tc + 4];
        #pragma unroll
        for (int nt = 0; nt < 8; nt++) {
            float b0 = ws[(n0b + nt*8 + gr) * 132 + ks*8 + tc];
            float b1 = ws[(n0b + nt*8 + gr) * 132 + ks*8 + tc + 4];
            mma8(c[nt],     a0, b0, b1);
            mma8(c[nt] + 4, a1, b0, b1);
        }
    }

    #pragma unroll
    for (int nt = 0; nt < 8; nt++) {
        int cch = n0b + nt*8 + 2*tc;
        float bb0 = bs[cch], bb1 = bs[cch + 1];
        float* base = out + ((size_t)b * LN) * CDIM + cch;
        #pragma unroll
        for (int mt = 0; mt < 2; mt++) {
            float* cr = c[nt] + mt*4;
            int r0 = mrow + mt * 16 + gr;
            *(float2*)(base +  r0      * CDIM) = make_float2(cr[0] + bb0, cr[1] + bb1);
            *(float2*)(base + (r0 + 8) * CDIM) = make_float2(cr[2] + bb0, cr[3] + bb1);
        }
    }
}

// =============================================================================
extern "C" void kernel_launch(void* const* d_in, const int* in_sizes, int n_in,
                              void* d_out, int out_size) {
    const float* x        = (const float*)d_in[0];
    const float* attn_msk = (const float*)d_in[1];
    const float* qkv_w    = (const float*)d_in[2];
    const float* qkv_b    = (const float*)d_in[3];
    const float* rpe      = (const float*)d_in[4];
    const float* proj_w   = (const float*)d_in[5];
    const float* proj_b   = (const float*)d_in[6];
    float* out = (float*)d_out;

    const int smem_k1   = (3*128*132 + 384) * sizeof(float);   // 204288
    const int smem_attn = 49120 * sizeof(float);               // 196480
    const int smem_k3   = (3*128*132 + 128) * sizeof(float);   // 203264

    cudaFuncSetAttribute(qkv_mma,     cudaFuncAttributeMaxDynamicSharedMemorySize, smem_k1);
    cudaFuncSetAttribute(attn_kernel, cudaFuncAttributeMaxDynamicSharedMemorySize, smem_attn);
    cudaFuncSetAttribute(proj_mma,    cudaFuncAttributeMaxDynamicSharedMemorySize, smem_k3);

    qkv_mma <<<B_TOT/2, 512, smem_k1>>>(x, qkv_w, qkv_b);
    attn_kernel<<<dim3(B_TOT, NH), 1024, smem_attn>>>(attn_msk, rpe);
    proj_mma<<<B_TOT/2, 512, smem_k3>>>(proj_w, proj_b, out);
}

// round 17
// speedup vs baseline: 1.4522x; 1.0078x over previous
#include <cuda_runtime.h>
#include <cuda_bf16.h>
#include <cstdint>

#define B_TOT 2048
#define LN    128
#define CDIM  128
#define NH    4
#define HD    32
#define SCALEF 0.17677669529663687f   // 32^-0.5

typedef unsigned long long ull;

// ---------- tf32 warp MMA ----------
__device__ __forceinline__ float tf32r(float f) {
    uint32_t u; asm("cvt.rna.tf32.f32 %0, %1;" : "=r"(u) : "f"(f));
    return __uint_as_float(u);
}
__device__ __forceinline__ void mma8(float* c, const float* a, float b0, float b1) {
    asm volatile(
        "mma.sync.aligned.m16n8k8.row.col.f32.tf32.tf32.f32 "
        "{%0,%1,%2,%3}, {%4,%5,%6,%7}, {%8,%9}, {%0,%1,%2,%3};"
        : "+f"(c[0]), "+f"(c[1]), "+f"(c[2]), "+f"(c[3])
        : "r"(__float_as_uint(a[0])), "r"(__float_as_uint(a[1])),
          "r"(__float_as_uint(a[2])), "r"(__float_as_uint(a[3])),
          "r"(__float_as_uint(b0)),  "r"(__float_as_uint(b1)));
}
__device__ __forceinline__ uint32_t bf16pk(float lo, float hi) {
    uint32_t r;
    asm("cvt.rn.bf16x2.f32 %0, %1, %2;" : "=r"(r) : "f"(hi), "f"(lo));
    return r;
}

// stage a 128x128 fp32 tile into smem stride-132 (tf32-rounded), 512 threads
__device__ __forceinline__ void stage128_512(float* dst, const float* __restrict__ src, int t) {
    const float4* g = (const float4*)src;
    #pragma unroll
    for (int r = 0; r < 8; r++) {
        int idx = r * 512 + t;
        float4 v = g[idx];
        int row = idx >> 5, col = (idx & 31) * 4;
        float* d = dst + row * 132 + col;
        d[0] = tf32r(v.x); d[1] = tf32r(v.y); d[2] = tf32r(v.z); d[3] = tf32r(v.w);
    }
}

// ------------------------- device scratch ---------------
__device__ float g_q [B_TOT*NH*LN*HD];
__device__ float g_k [B_TOT*NH*LN*HD];
__device__ float g_v [B_TOT*NH*LN*HD];
__device__ float g_oh[B_TOT*LN*CDIM];

// =============================================================================
// K1 (warp-MMA tf32, 2 windows/block) — unchanged from passing R12.
// =============================================================================
__global__ __launch_bounds__(512) void qkv_mma(const float* __restrict__ x,
                                               const float* __restrict__ w,
                                               const float* __restrict__ bias) {
    extern __shared__ float sm[];
    float* xs = sm;
    float* ws = sm + 2*128*132;
    float* bs = sm + 3*128*132;
    const int t = threadIdx.x;
    const int wid = t >> 5, lane = t & 31;
    const int gr = lane >> 2, tc = lane & 3;
    const int w_i  = wid >> 3;
    const int wid8 = wid & 7;
    const int mrow = (wid8 & 3) * 32;
    const int n0b  = (wid8 >> 2) * 64;
    const int b = blockIdx.x * 2 + w_i;
    float* xw = xs + w_i * (128*132);

    stage128_512(xs,           x + (size_t)(blockIdx.x*2)     * 16384, t);
    stage128_512(xs + 128*132, x + (size_t)(blockIdx.x*2 + 1) * 16384, t);
    if (t < 384) bs[t] = bias[t];

    for (int cc = 0; cc < 3; cc++) {
        __syncthreads();
        stage128_512(ws, w + cc * 16384, t);
        __syncthreads();

        float* arr = (cc == 0) ? g_q : ((cc == 1) ? g_k : g_v);
        const float scl = (cc == 0) ? SCALEF : 1.0f;

        float c[8][8];
        #pragma unroll
        for (int nt = 0; nt < 8; nt++) {
            #pragma unroll
            for (int u = 0; u < 8; u++) c[nt][u] = 0.f;
        }

        #pragma unroll
        for (int ks = 0; ks < 16; ks++) {
            float a0[4], a1[4];
            a0[0] = xw[(mrow + gr)      * 132 + ks*8 + tc];
            a0[1] = xw[(mrow + gr + 8)  * 132 + ks*8 + tc];
            a0[2] = xw[(mrow + gr)      * 132 + ks*8 + tc + 4];
            a0[3] = xw[(mrow + gr + 8)  * 132 + ks*8 + tc + 4];
            a1[0] = xw[(mrow + gr + 16) * 132 + ks*8 + tc];
            a1[1] = xw[(mrow + gr + 24) * 132 + ks*8 + tc];
            a1[2] = xw[(mrow + gr + 16) * 132 + ks*8 + tc + 4];
            a1[3] = xw[(mrow + gr + 24) * 132 + ks*8 + tc + 4];
            #pragma unroll
            for (int nt = 0; nt < 8; nt++) {
                float b0 = ws[(n0b + nt*8 + gr) * 132 + ks*8 + tc];
                float b1 = ws[(n0b + nt*8 + gr) * 132 + ks*8 + tc + 4];
                mma8(c[nt],     a0, b0, b1);
                mma8(c[nt] + 4, a1, b0, b1);
            }
        }

        #pragma unroll
        for (int nt = 0; nt < 8; nt++) {
            int cch = n0b + nt*8 + 2*tc;
            float bb0 = bs[cc*128 + cch], bb1 = bs[cc*128 + cch + 1];
            int h = cch >> 5, ch = cch & 31;
            float* base = arr + (((size_t)b * NH + h) * LN) * HD + ch;
            #pragma unroll
            for (int mt = 0; mt < 2; mt++) {
                float* cr = c[nt] + mt*4;
                int r0 = mrow + mt * 16 + gr;
                *(float2*)(base +  r0      * HD) = make_float2((cr[0]+bb0)*scl, (cr[1]+bb1)*scl);
                *(float2*)(base + (r0 + 8) * HD) = make_float2((cr[2]+bb0)*scl, (cr[3]+bb1)*scl);
            }
        }
    }
}

// =============================================================================
// K2 v7: 6-barrier structure. QR+KR GEMMs merged (both bf16 out); merged
// single-barrier softmax; zero-W folded in. 1024 threads / 32 warps.
// smem floats: q_s@0 4608 | k_s@4608 | tabq@9216 8640 | tab@17856 8352 |
//   QRb(bf16)@26208 7936 / S f32 @26208 16640 | KRb(bf16)@34144 15488 |
//   vt@49632 4224 | redm@53856 1024 | reds@54880 1024 | rr@55904 128
//   total 56032 floats = 224128 B.   W[128][122] overlays q_s/k_s/tabq.
// =============================================================================
__global__ __launch_bounds__(1024, 1) void attn_kernel(const float* __restrict__ mask,
                                                       const float* __restrict__ rpe) {
    extern __shared__ float sm[];
    float* q_s  = sm;
    float* k_s  = sm + 4608;
    float* tabq = sm + 9216;       // [240][36] tf32, rows 225+ zero
    float* tab  = sm + 17856;      // tabk [225][36] -> tabv^T [32][233]
    float* S    = sm + 26208;      // f32 [128][130] (after gathers)
    float* vt   = sm + 49632;      // [32][132] tf32 V^T
    float* redm = sm + 53856;      // [1024] local max
    float* reds = sm + 54880;      // [1024] local sum
    float* rr   = sm + 55904;      // [128] rinv
    float* W    = sm;              // [128][122] overlays q_s/k_s/tabq
    __nv_bfloat16* QRb = (__nv_bfloat16*)(sm + 26208);   // [128][124]
    __nv_bfloat16* KRb = (__nv_bfloat16*)(sm + 34144);   // [128][242]

    const int b = blockIdx.x, h = blockIdx.y;
    const int t  = threadIdx.x;
    const int i  = t & 127;
    const int jq = t >> 7;         // 0..7
    const int wid = t >> 5, lane = t & 31;
    const int gr = lane >> 2, tc = lane & 3;
    const int ms = wid & 7;
    const int nq = wid >> 3;

    // ---- P0: stage q,k (tf32), tabq, tabk, V^T; att=mask ----
    {
        const float4* kg = (const float4*)(g_k + (((size_t)b*NH + h)*LN)*HD);
        const float4* qg = (const float4*)(g_q + (((size_t)b*NH + h)*LN)*HD);
        int idx4 = t;
        float4 kv = kg[idx4], qv4 = qg[idx4];
        int row = idx4 >> 3, c4 = (idx4 & 7) * 4;
        float* dk = k_s + row*36 + c4;
        float* dq = q_s + row*36 + c4;
        dk[0] = tf32r(kv.x);  dk[1] = tf32r(kv.y);  dk[2] = tf32r(kv.z);  dk[3] = tf32r(kv.w);
        dq[0] = tf32r(qv4.x); dq[1] = tf32r(qv4.y); dq[2] = tf32r(qv4.z); dq[3] = tf32r(qv4.w);

        const float* vbase = g_v + (((size_t)b*NH + h)*LN)*HD;
        #pragma unroll
        for (int r = 0; r < 4; r++) {
            int idx = r*1024 + t;
            int j = idx >> 5, c = idx & 31;
            vt[c*132 + j] = tf32r(vbase[idx]);
        }
    }
    for (int idx = t; idx < 7680; idx += 1024) {
        int r = idx >> 5, u = idx & 31;
        tabq[r*36 + u] = (r < 225) ? tf32r(rpe[r*384 + h*96 + u] * SCALEF) : 0.f;
    }
    for (int idx = t; idx < 7200; idx += 1024) {
        int r = idx >> 5, u = idx & 31;
        tab[r*36 + u] = tf32r(rpe[r*384 + h*96 + 32 + u]);
    }
    float att[16];
    {
        const float4* mp = (const float4*)(mask + (size_t)(b & 127)*LN*LN + i*LN + jq*16);
        #pragma unroll
        for (int u = 0; u < 4; u++) {
            float4 m4 = mp[u];
            att[u*4+0] = m4.x; att[u*4+1] = m4.y; att[u*4+2] = m4.z; att[u*4+3] = m4.w;
        }
    }
    __syncthreads();                                   // (1)

    const int hi = i >> 4;
    const int wi = (i >> 1) & 7;

    // ---- P1: QR GEMM (banded) -> QRb bf16 AND KR GEMM (full) -> KRb bf16 ----
    {
        float fa[4][4];
        #pragma unroll
        for (int ks = 0; ks < 4; ks++) {
            fa[ks][0] = q_s[(ms*16 + gr)     * 36 + ks*8 + tc];
            fa[ks][1] = q_s[(ms*16 + gr + 8) * 36 + ks*8 + tc];
            fa[ks][2] = q_s[(ms*16 + gr)     * 36 + ks*8 + tc + 4];
            fa[ks][3] = q_s[(ms*16 + gr + 8) * 36 + ks*8 + tc + 4];
        }
        int nt_end = nq*4 + 4; if (nt_end > 15) nt_end = 15;
        for (int nt = nq*4; nt < nt_end; nt++) {
            float c4[4] = {0.f, 0.f, 0.f, 0.f};
            #pragma unroll
            for (int ks = 0; ks < 4; ks++) {
                int trow = ms*15 + nt*8 + gr;
                float b0 = tab[trow*36 + ks*8 + tc];
                float b1 = tab[trow*36 + ks*8 + tc + 4];
                mma8(c4, fa[ks], b0, b1);
            }
            int col = nt*8 + 2*tc;
            int r0 = ms*16 + gr;
            *(uint32_t*)(QRb +  r0      * 124 + col) = bf16pk(c4[0], c4[1]);
            *(uint32_t*)(QRb + (r0 + 8) * 124 + col) = bf16pk(c4[2], c4[3]);
        }
        // KR: k fragments
        #pragma unroll
        for (int ks = 0; ks < 4; ks++) {
            fa[ks][0] = k_s[(ms*16 + gr)     * 36 + ks*8 + tc];
            fa[ks][1] = k_s[(ms*16 + gr + 8) * 36 + ks*8 + tc];
            fa[ks][2] = k_s[(ms*16 + gr)     * 36 + ks*8 + tc + 4];
            fa[ks][3] = k_s[(ms*16 + gr + 8) * 36 + ks*8 + tc + 4];
        }
        for (int nt = nq; nt < 30; nt += 4) {
            float c4[4] = {0.f, 0.f, 0.f, 0.f};
            #pragma unroll
            for (int ks = 0; ks < 4; ks++) {
                int trow = nt*8 + gr;
                float b0 = tabq[trow*36 + ks*8 + tc];
                float b1 = tabq[trow*36 + ks*8 + tc + 4];
                mma8(c4, fa[ks], b0, b1);
            }
            int col = nt*8 + 2*tc;
            int r0 = ms*16 + gr;
            *(uint32_t*)(KRb +  r0      * 242 + col) = bf16pk(c4[0], c4[1]);
            *(uint32_t*)(KRb + (r0 + 8) * 242 + col) = bf16pk(c4[2], c4[3]);
        }
    }
    __syncthreads();                                   // (2)

    // ---- P2: gather QR + KR; stage tabv^T ----
    #pragma unroll
    for (int jj = 0; jj < 8; jj++) {
        int pj = jq*8 + jj;
        int lidx = (7 - (pj >> 3))*15 + (wi - (pj & 7) + 7);
        int ridx = (hi - (pj >> 3) + 7)*15 + (wi - (pj & 7) + 7);
        float qr = __bfloat162float(QRb[i*124 + lidx]);
        att[2*jj]   += qr + __bfloat162float(KRb[(2*pj)    *242 + ridx]);
        att[2*jj+1] += qr + __bfloat162float(KRb[(2*pj + 1)*242 + ridx]);
    }
    for (int idx = t; idx < 7200; idx += 1024) {
        int tt = idx >> 5, u = idx & 31;
        tab[u*233 + tt] = tf32r(rpe[tt*384 + h*96 + 64 + u]);      // v_rpe^T
    }
    __syncthreads();                                   // (3)

    // ---- P3: QK GEMM -> S f32 stride 130 ----
    {
        float fa[4][4];
        #pragma unroll
        for (int ks = 0; ks < 4; ks++) {
            fa[ks][0] = q_s[(ms*16 + gr)     * 36 + ks*8 + tc];
            fa[ks][1] = q_s[(ms*16 + gr + 8) * 36 + ks*8 + tc];
            fa[ks][2] = q_s[(ms*16 + gr)     * 36 + ks*8 + tc + 4];
            fa[ks][3] = q_s[(ms*16 + gr + 8) * 36 + ks*8 + tc + 4];
        }
        #pragma unroll
        for (int nn = 0; nn < 4; nn++) {
            int nt = nq*4 + nn;
            float c4[4] = {0.f, 0.f, 0.f, 0.f};
            #pragma unroll
            for (int ks = 0; ks < 4; ks++) {
                int krow = nt*8 + gr;
                float b0 = k_s[krow*36 + ks*8 + tc];
                float b1 = k_s[krow*36 + ks*8 + tc + 4];
                mma8(c4, fa[ks], b0, b1);
            }
            int col = nt*8 + 2*tc;
            *(float2*)(S + (ms*16 + gr)     * 130 + col) = make_float2(c4[0], c4[1]);
            *(float2*)(S + (ms*16 + gr + 8) * 130 + col) = make_float2(c4[2], c4[3]);
        }
    }
    __syncthreads();                                   // (4)

    // ---- P4: att += S; local max/sum; zero W ----
    #pragma unroll
    for (int u = 0; u < 16; u++) att[u] += S[i*130 + jq*16 + u];

    float lm = att[0];
    #pragma unroll
    for (int u = 1; u < 16; u++) lm = fmaxf(lm, att[u]);
    float ls = 0.f;
    #pragma unroll
    for (int u = 0; u < 16; u++) { float e = __expf(att[u] - lm); att[u] = e; ls += e; }
    redm[jq*128 + i] = lm;
    reds[jq*128 + i] = ls;
    {
        float4 z = make_float4(0.f, 0.f, 0.f, 0.f);
        float4* s4 = (float4*)W;
        #pragma unroll
        for (int r = 0; r < 4; r++) {
            int idx = r*1024 + t;
            if (idx < 3904) s4[idx] = z;
        }
    }
    __syncthreads();                                   // (5)

    // ---- P5: global softmax fixup; write P (tf32) and scatter W ----
    {
        float M = redm[i];
        #pragma unroll
        for (int p = 1; p < 8; p++) M = fmaxf(M, redm[p*128 + i]);
        float denom = 0.f;
        #pragma unroll
        for (int p = 0; p < 8; p++) denom += reds[p*128 + i] * __expf(redm[p*128 + i] - M);
        float f = __expf(lm - M);
        #pragma unroll
        for (int u = 0; u < 16; u++) att[u] *= f;
        if (jq == 0) rr[i] = 1.0f / denom;
    }
    #pragma unroll
    for (int u = 0; u < 16; u++) S[i*130 + jq*16 + u] = tf32r(att[u]);
    #pragma unroll
    for (int jj = 0; jj < 8; jj++) {
        int pj = jq*8 + jj;
        int lidx = (7 - (pj >> 3))*15 + (wi - (pj & 7) + 7);
        W[i*122 + lidx] = tf32r(att[2*jj] + att[2*jj+1]);
    }
    __syncthreads();                                   // (6)

    // ---- P6: fused O = P@V + W@tabv, x rinv, -> g_oh ----
    {
        float c4[4] = {0.f, 0.f, 0.f, 0.f};
        for (int ks = 0; ks < 16; ks++) {       // P@V, K=128
            float wa[4];
            wa[0] = S[(ms*16 + gr)     * 130 + ks*8 + tc];
            wa[1] = S[(ms*16 + gr + 8) * 130 + ks*8 + tc];
            wa[2] = S[(ms*16 + gr)     * 130 + ks*8 + tc + 4];
            wa[3] = S[(ms*16 + gr + 8) * 130 + ks*8 + tc + 4];
            int vrow = nq*8 + gr;
            float b0 = vt[vrow*132 + ks*8 + tc];
            float b1 = vt[vrow*132 + ks*8 + tc + 4];
            mma8(c4, wa, b0, b1);
        }
        for (int ks = 0; ks < 15; ks++) {       // W@tabv, banded K=120
            float wa[4];
            wa[0] = W[(ms*16 + gr)     * 122 + ks*8 + tc];
            wa[1] = W[(ms*16 + gr + 8) * 122 + ks*8 + tc];
            wa[2] = W[(ms*16 + gr)     * 122 + ks*8 + tc + 4];
            wa[3] = W[(ms*16 + gr + 8) * 122 + ks*8 + tc + 4];
            int crow = nq*8 + gr;
            float b0 = tab[crow*233 + ms*15 + ks*8 + tc];
            float b1 = tab[crow*233 + ms*15 + ks*8 + tc + 4];
            mma8(c4, wa, b0, b1);
        }
        int r0 = ms*16 + gr;
        float rinv0 = rr[r0], rinv1 = rr[r0 + 8];
        int col = nq*8 + 2*tc;
        float* base = g_oh + ((size_t)b*LN)*CDIM + h*HD + col;
        *(float2*)(base +  r0      * CDIM) = make_float2(c4[0]*rinv0, c4[1]*rinv0);
        *(float2*)(base + (r0 + 8) * CDIM) = make_float2(c4[2]*rinv1, c4[3]*rinv1);
    }
}

// =============================================================================
// K3 (warp-MMA tf32, 2 windows/block) — unchanged from passing R12.
// =============================================================================
__global__ __launch_bounds__(512) void proj_mma(const float* __restrict__ w,
                                                const float* __restrict__ bias,
                                                float* __restrict__ out) {
    extern __shared__ float sm[];
    float* xs = sm;
    float* ws = sm + 2*128*132;
    float* bs = sm + 3*128*132;
    const int t = threadIdx.x;
    const int wid = t >> 5, lane = t & 31;
    const int gr = lane >> 2, tc = lane & 3;
    const int w_i  = wid >> 3;
    const int wid8 = wid & 7;
    const int mrow = (wid8 & 3) * 32;
    const int n0b  = (wid8 >> 2) * 64;
    const int b = blockIdx.x * 2 + w_i;
    float* xw = xs + w_i * (128*132);

    stage128_512(xs,           g_oh + (size_t)(blockIdx.x*2)     * 16384, t);
    stage128_512(xs + 128*132, g_oh + (size_t)(blockIdx.x*2 + 1) * 16384, t);
    stage128_512(ws, w, t);
    if (t < 128) bs[t] = bias[t];
    __syncthreads();

    float c[8][8];
    #pragma unroll
    for (int nt = 0; nt < 8; nt++) {
        #pragma unroll
        for (int u = 0; u < 8; u++) c[nt][u] = 0.f;
    }

    #pragma unroll
    for (int ks = 0; ks < 16; ks++) {
        float a0[4], a1[4];
        a0[0] = xw[(mrow + gr)      * 132 + ks*8 + tc];
        a0[1] = xw[(mrow + gr + 8)  * 132 + ks*8 + tc];
        a0[2] = xw[(mrow + gr)      * 132 + ks*8 + tc + 4];
        a0[3] = xw[(mrow + gr + 8)  * 132 + ks*8 + tc + 4];
        a1[0] = xw[(mrow + gr + 16) * 132 + ks*8 + tc];
        a1[1] = xw[(mrow + gr + 24) * 132 + ks*8 + tc];
        a1[2] = xw[(mrow + gr + 16) * 132 + ks*8 + tc + 4];
        a1[3] = xw[(mrow + gr + 24) * 132 + ks*8 + tc + 4];
        #pragma unroll
        for (int nt = 0; nt < 8; nt++) {
            float b0 = ws[(n0b + nt*8 + gr) * 132 + ks*8 + tc];
            float b1 = ws[(n0b + nt*8 + gr) * 132 + ks*8 + tc + 4];
            mma8(c[nt],     a0, b0, b1);
            mma8(c[nt] + 4, a1, b0, b1);
        }
    }

    #pragma unroll
    for (int nt = 0; nt < 8; nt++) {
        int cch = n0b + nt*8 + 2*tc;
        float bb0 = bs[cch], bb1 = bs[cch + 1];
        float* base = out + ((size_t)b * LN) * CDIM + cch;
        #pragma unroll
        for (int mt = 0; mt < 2; mt++) {
            float* cr = c[nt] + mt*4;
            int r0 = mrow + mt * 16 + gr;
            *(float2*)(base +  r0      * CDIM) = make_float2(cr[0] + bb0, cr[1] + bb1);
            *(float2*)(base + (r0 + 8) * CDIM) = make_float2(cr[2] + bb0, cr[3] + bb1);
        }
    }
}

// =============================================================================
extern "C" void kernel_launch(void* const* d_in, const int* in_sizes, int n_in,
                              void* d_out, int out_size) {
    const float* x        = (const float*)d_in[0];
    const float* attn_msk = (const float*)d_in[1];
    const float* qkv_w    = (const float*)d_in[2];
    const float* qkv_b    = (const float*)d_in[3];
    const float* rpe      = (const float*)d_in[4];
    const float* proj_w   = (const float*)d_in[5];
    const float* proj_b   = (const float*)d_in[6];
    float* out = (float*)d_out;

    const int smem_k1   = (3*128*132 + 384) * sizeof(float);   // 204288
    const int smem_attn = 56032 * sizeof(float);               // 224128
    const int smem_k3   = (3*128*132 + 128) * sizeof(float);   // 203264

    cudaFuncSetAttribute(qkv_mma,     cudaFuncAttributeMaxDynamicSharedMemorySize, smem_k1);
    cudaFuncSetAttribute(attn_kernel, cudaFuncAttributeMaxDynamicSharedMemorySize, smem_attn);
    cudaFuncSetAttribute(proj_mma,    cudaFuncAttributeMaxDynamicSharedMemorySize, smem_k3);

    qkv_mma <<<B_TOT/2, 512, smem_k1>>>(x, qkv_w, qkv_b);
    attn_kernel<<<dim3(B_TOT, NH), 1024, smem_attn>>>(attn_msk, rpe);
    proj_mma<<<B_TOT/2, 512, smem_k3>>>(proj_w, proj_b, out);
}